// round 2
// baseline (speedup 1.0000x reference)
#include <cuda_runtime.h>

// ---------------- static problem constants ----------------
#define HH 495
#define WW 436
#define NN (HH*WW)            // 215820 nodes
#define PRR 248               // pooled rows
#define PCC 218               // pooled cols
#define NP (PRR*PCC)          // 54064 pooled nodes
#define E_NS ((HH-1)*WW)      // 215384 edges (north & south)
#define E_EW (HH*(WW-1))      // 215325 edges (east & west)
#define M_NS (247*218)        // 53846 kept pooled edges (n, s)
#define M_EW (248*217)        // 53816 kept pooled edges (e, w)

// output layout (float elements)
#define OFF_POS 6920192
#define OFF_EIN 7028320
#define OFF_EIE 7136012
#define OFF_EIS 7243644
#define OFF_EIW 7351336
#define OFF_FN  7458968
#define OFF_FE  9182040
#define OFF_FS  10904152
#define OFF_FW  12627224
#define OUT_TOTAL 14349336

#define PAD 132   // smem A-tile row stride (floats): 132*4B = 528B, 16B aligned, low-conflict

// ---------------- scratch (device globals; no allocs allowed) ----------------
__device__ float g_XQ[(size_t)NN*128];        // relu(x @ Wemb) all 4 quadrants
__device__ float g_EDGE[4][(size_t)E_NS*32];  // per-direction edge MLP outputs
__device__ float g_X2[(size_t)NN*128];        // node GEMM output

// ---------------- f32x2 helpers (exact fp32, 2x fma-pipe throughput) ----------------
__device__ __forceinline__ unsigned long long pk2(float x, float y){
    unsigned long long r;
    asm("mov.b64 %0, {%1,%2};" : "=l"(r) : "f"(x), "f"(y));
    return r;
}
__device__ __forceinline__ void upk(unsigned long long v, float &x, float &y){
    asm("mov.b64 {%0,%1}, %2;" : "=f"(x), "=f"(y) : "l"(v));
}
__device__ __forceinline__ void ffma2(unsigned long long &d, unsigned long long a, unsigned long long b){
    asm("fma.rn.f32x2 %0, %1, %2, %0;" : "+l"(d) : "l"(a), "l"(b));
}

// =====================================================================
// GEMM1: XQ = relu(x[N,128] @ Wcat[128,128]),  Wcat[:, q*32+u] = W_emb[q][:,u]
// tile 128x128, 256 threads, TM=8 TN=8, K chunks of 32
// =====================================================================
__global__ __launch_bounds__(256) void k_gemm1(const float* __restrict__ x,
                                               const float* __restrict__ Wemb){
    __shared__ float As[32*PAD];
    __shared__ float Bs[32*128];
    const int tid = threadIdx.x;
    const int M0  = blockIdx.x * 128;
    const int tx = tid & 15, ty = tid >> 4;

    unsigned long long acc[8][4];
#pragma unroll
    for (int i = 0; i < 8; i++)
#pragma unroll
        for (int j = 0; j < 4; j++) acc[i][j] = 0ull;

    for (int kc = 0; kc < 4; kc++){
        // A tile (transposed store: As[k][m])
#pragma unroll
        for (int i = 0; i < 4; i++){
            int lin = tid + 256*i;
            int m = lin >> 3, k4 = (lin & 7) * 4;
            int gm = M0 + m;
            float4 v = make_float4(0.f,0.f,0.f,0.f);
            if (gm < NN) v = *(const float4*)(x + (size_t)gm*128 + kc*32 + k4);
            As[(k4+0)*PAD + m] = v.x;
            As[(k4+1)*PAD + m] = v.y;
            As[(k4+2)*PAD + m] = v.z;
            As[(k4+3)*PAD + m] = v.w;
        }
        // B tile: Bs[k][j] = Wemb[q=j>>5][kc*32+k][j&31]
#pragma unroll
        for (int i = 0; i < 4; i++){
            int lin = tid + 256*i;
            int k = lin >> 5, j = (lin & 31) * 4;
            int q = j >> 5, u = j & 31;
            float4 v = *(const float4*)(Wemb + q*4096 + (kc*32 + k)*32 + u);
            *(float4*)(Bs + k*128 + j) = v;
        }
        __syncthreads();
#pragma unroll
        for (int k = 0; k < 32; k++){
            float4 a0 = *(const float4*)(As + k*PAD + ty*8);
            float4 a1 = *(const float4*)(As + k*PAD + ty*8 + 4);
            ulonglong2 b0 = *(const ulonglong2*)(Bs + k*128 + tx*8);
            ulonglong2 b1 = *(const ulonglong2*)(Bs + k*128 + tx*8 + 4);
            unsigned long long ad[8];
            ad[0]=pk2(a0.x,a0.x); ad[1]=pk2(a0.y,a0.y); ad[2]=pk2(a0.z,a0.z); ad[3]=pk2(a0.w,a0.w);
            ad[4]=pk2(a1.x,a1.x); ad[5]=pk2(a1.y,a1.y); ad[6]=pk2(a1.z,a1.z); ad[7]=pk2(a1.w,a1.w);
#pragma unroll
            for (int i = 0; i < 8; i++){
                ffma2(acc[i][0], ad[i], b0.x);
                ffma2(acc[i][1], ad[i], b0.y);
                ffma2(acc[i][2], ad[i], b1.x);
                ffma2(acc[i][3], ad[i], b1.y);
            }
        }
        __syncthreads();
    }
#pragma unroll
    for (int i = 0; i < 8; i++){
        int gm = M0 + ty*8 + i;
        if (gm >= NN) break;
        float o[8];
#pragma unroll
        for (int jp = 0; jp < 4; jp++) upk(acc[i][jp], o[2*jp], o[2*jp+1]);
#pragma unroll
        for (int j = 0; j < 8; j++) o[j] = fmaxf(o[j], 0.f);
        *(float4*)(g_XQ + (size_t)gm*128 + tx*8)     = make_float4(o[0],o[1],o[2],o[3]);
        *(float4*)(g_XQ + (size_t)gm*128 + tx*8 + 4) = make_float4(o[4],o[5],o[6],o[7]);
    }
}

// =====================================================================
// Edge GEMM: EDGE[q][e] = relu([ef[e] | XQ[src,q] | XQ[dst,q]] @ W_edge[q])
// tile 128 edges x 32 outs, K=96 (3 chunks of 32), 256 threads, TM=4 TN=4
// blockIdx.y = direction q
// =====================================================================
__global__ __launch_bounds__(256) void k_edge(const float* __restrict__ efN,
                                              const float* __restrict__ efE,
                                              const float* __restrict__ efS,
                                              const float* __restrict__ efW,
                                              const float* __restrict__ Wedge){
    const int q = blockIdx.y;
    const float* ef = (q==0) ? efN : (q==1) ? efE : (q==2) ? efS : efW;
    const int E = (q==0 || q==2) ? E_NS : E_EW;
    const int M0 = blockIdx.x * 128;
    if (M0 >= E) return;

    __shared__ float As[32*PAD];
    __shared__ float Bs[32*32];
    const int tid = threadIdx.x;
    const int tx = tid & 7, ty = tid >> 3;

    unsigned long long acc[4][2];
#pragma unroll
    for (int i = 0; i < 4; i++){ acc[i][0] = 0ull; acc[i][1] = 0ull; }

    for (int kc = 0; kc < 3; kc++){
#pragma unroll
        for (int i = 0; i < 4; i++){
            int lin = tid + 256*i;
            int m = lin >> 3, k4 = (lin & 7) * 4;
            int e = M0 + m;
            float4 v = make_float4(0.f,0.f,0.f,0.f);
            if (e < E){
                if (kc == 0){
                    v = *(const float4*)(ef + (size_t)e*32 + k4);
                } else {
                    int s, t;
                    if (q == 0){ int r = 1 + e/WW,     c = e%WW;         s = r*WW + c; t = s - WW; }
                    else if (q == 1){ int r = e/(WW-1), c = e%(WW-1);    s = r*WW + c; t = s + 1;  }
                    else if (q == 2){ int r = e/WW,     c = e%WW;        s = r*WW + c; t = s + WW; }
                    else            { int r = e/(WW-1), c = e%(WW-1)+1;  s = r*WW + c; t = s - 1;  }
                    int node = (kc == 1) ? s : t;
                    v = *(const float4*)(g_XQ + (size_t)node*128 + q*32 + k4);
                }
            }
            As[(k4+0)*PAD + m] = v.x;
            As[(k4+1)*PAD + m] = v.y;
            As[(k4+2)*PAD + m] = v.z;
            As[(k4+3)*PAD + m] = v.w;
        }
        {   // B: 32x32 = 256 float4, one per thread
            int k = tid >> 3, j = (tid & 7) * 4;
            *(float4*)(Bs + k*32 + j) = *(const float4*)(Wedge + q*3072 + (kc*32 + k)*32 + j);
        }
        __syncthreads();
#pragma unroll
        for (int k = 0; k < 32; k++){
            float4 a = *(const float4*)(As + k*PAD + ty*4);
            ulonglong2 b = *(const ulonglong2*)(Bs + k*32 + tx*4);
            unsigned long long ad0 = pk2(a.x,a.x), ad1 = pk2(a.y,a.y),
                               ad2 = pk2(a.z,a.z), ad3 = pk2(a.w,a.w);
            ffma2(acc[0][0], ad0, b.x); ffma2(acc[0][1], ad0, b.y);
            ffma2(acc[1][0], ad1, b.x); ffma2(acc[1][1], ad1, b.y);
            ffma2(acc[2][0], ad2, b.x); ffma2(acc[2][1], ad2, b.y);
            ffma2(acc[3][0], ad3, b.x); ffma2(acc[3][1], ad3, b.y);
        }
        __syncthreads();
    }
    float* ED = &g_EDGE[q][0];
#pragma unroll
    for (int i = 0; i < 4; i++){
        int e = M0 + ty*4 + i;
        if (e >= E) break;
        float o0,o1,o2,o3;
        upk(acc[i][0], o0, o1); upk(acc[i][1], o2, o3);
        *(float4*)(ED + (size_t)e*32 + tx*4) =
            make_float4(fmaxf(o0,0.f), fmaxf(o1,0.f), fmaxf(o2,0.f), fmaxf(o3,0.f));
    }
}

// =====================================================================
// GEMM2: X2 = relu([x | agg_n | agg_e | agg_s | agg_w] @ W_node[256,128])
// agg gathered from EDGE (one in-edge per node per direction); SCALE folded into B
// =====================================================================
__global__ __launch_bounds__(256) void k_gemm2(const float* __restrict__ x,
                                               const float* __restrict__ Wnode){
    __shared__ float As[32*PAD];
    __shared__ float Bs[32*128];
    const int tid = threadIdx.x;
    const int M0  = blockIdx.x * 128;
    const int tx = tid & 15, ty = tid >> 4;

    unsigned long long acc[8][4];
#pragma unroll
    for (int i = 0; i < 8; i++)
#pragma unroll
        for (int j = 0; j < 4; j++) acc[i][j] = 0ull;

    for (int kc = 0; kc < 8; kc++){
#pragma unroll
        for (int i = 0; i < 4; i++){
            int lin = tid + 256*i;
            int m = lin >> 3, k4 = (lin & 7) * 4;
            int gm = M0 + m;
            float4 v = make_float4(0.f,0.f,0.f,0.f);
            if (gm < NN){
                if (kc < 4){
                    v = *(const float4*)(x + (size_t)gm*128 + kc*32 + k4);
                } else {
                    int d = kc - 4;
                    int r = gm / WW, c = gm - r*WW;
                    int e = -1;
                    if (d == 0){ if (r < HH-1) e = gm; }                 // north in-edge
                    else if (d == 1){ if (c >= 1) e = r*(WW-1) + c - 1; } // east
                    else if (d == 2){ if (r >= 1) e = gm - WW; }          // south
                    else            { if (c <= WW-2) e = r*(WW-1) + c; }  // west
                    if (e >= 0) v = *(const float4*)(&g_EDGE[d][0] + (size_t)e*32 + k4);
                }
            }
            As[(k4+0)*PAD + m] = v.x;
            As[(k4+1)*PAD + m] = v.y;
            As[(k4+2)*PAD + m] = v.z;
            As[(k4+3)*PAD + m] = v.w;
        }
#pragma unroll
        for (int i = 0; i < 4; i++){
            int lin = tid + 256*i;
            int k = lin >> 5, j = (lin & 31) * 4;
            float4 v = *(const float4*)(Wnode + (kc*32 + k)*128 + j);
            if (kc >= 4){ v.x *= 0.25f; v.y *= 0.25f; v.z *= 0.25f; v.w *= 0.25f; }
            *(float4*)(Bs + k*128 + j) = v;
        }
        __syncthreads();
#pragma unroll
        for (int k = 0; k < 32; k++){
            float4 a0 = *(const float4*)(As + k*PAD + ty*8);
            float4 a1 = *(const float4*)(As + k*PAD + ty*8 + 4);
            ulonglong2 b0 = *(const ulonglong2*)(Bs + k*128 + tx*8);
            ulonglong2 b1 = *(const ulonglong2*)(Bs + k*128 + tx*8 + 4);
            unsigned long long ad[8];
            ad[0]=pk2(a0.x,a0.x); ad[1]=pk2(a0.y,a0.y); ad[2]=pk2(a0.z,a0.z); ad[3]=pk2(a0.w,a0.w);
            ad[4]=pk2(a1.x,a1.x); ad[5]=pk2(a1.y,a1.y); ad[6]=pk2(a1.z,a1.z); ad[7]=pk2(a1.w,a1.w);
#pragma unroll
            for (int i = 0; i < 8; i++){
                ffma2(acc[i][0], ad[i], b0.x);
                ffma2(acc[i][1], ad[i], b0.y);
                ffma2(acc[i][2], ad[i], b1.x);
                ffma2(acc[i][3], ad[i], b1.y);
            }
        }
        __syncthreads();
    }
#pragma unroll
    for (int i = 0; i < 8; i++){
        int gm = M0 + ty*8 + i;
        if (gm >= NN) break;
        float o[8];
#pragma unroll
        for (int jp = 0; jp < 4; jp++) upk(acc[i][jp], o[2*jp], o[2*jp+1]);
#pragma unroll
        for (int j = 0; j < 8; j++) o[j] = fmaxf(o[j], 0.f);
        *(float4*)(g_X2 + (size_t)gm*128 + tx*8)     = make_float4(o[0],o[1],o[2],o[3]);
        *(float4*)(g_X2 + (size_t)gm*128 + tx*8 + 4) = make_float4(o[4],o[5],o[6],o[7]);
    }
}

// =====================================================================
// 2x2 pooling: x_pooled[p] = max over cell nodes of X2 (last pooled row has 2 nodes)
// =====================================================================
template<typename T>
__global__ void k_pool(T* __restrict__ out){
    int t = blockIdx.x * 256 + threadIdx.x;
    if (t >= NP * 32) return;
    int p = t >> 5, fi = (t & 31) * 4;
    int pr = p / PCC, pc = p % PCC;
    int n00 = (2*pr)*WW + 2*pc;
    const float* base = g_X2 + (size_t)n00*128 + fi;
    float4 a = *(const float4*)(base);
    float4 b = *(const float4*)(base + 128);
    a.x = fmaxf(a.x, b.x); a.y = fmaxf(a.y, b.y);
    a.z = fmaxf(a.z, b.z); a.w = fmaxf(a.w, b.w);
    if (2*pr + 1 < HH){
        float4 c4 = *(const float4*)(base + (size_t)128*WW);
        float4 d4 = *(const float4*)(base + (size_t)128*WW + 128);
        a.x = fmaxf(a.x, fmaxf(c4.x, d4.x));
        a.y = fmaxf(a.y, fmaxf(c4.y, d4.y));
        a.z = fmaxf(a.z, fmaxf(c4.z, d4.z));
        a.w = fmaxf(a.w, fmaxf(c4.w, d4.w));
    }
    T* o = out + (size_t)p*128 + fi;
    o[0] = (T)a.x; o[1] = (T)a.y; o[2] = (T)a.z; o[3] = (T)a.w;
}

// =====================================================================
// Static metadata: new_pos + 4x new_eidx (all closed-form)
// =====================================================================
template<typename T>
__global__ void k_meta(T* __restrict__ out){
    int t = blockIdx.x * 256 + threadIdx.x;
    if (t < NP){
        out[OFF_POS + 2*t]     = (T)(t / PCC);
        out[OFF_POS + 2*t + 1] = (T)(t % PCC);
        return;
    }
    t -= NP;
    if (t < M_NS){ // north: (k*218+j, (k-1)*218+j), k=1..247
        int k = 1 + t / PCC, j = t % PCC;
        out[OFF_EIN + 2*t]     = (T)(k*PCC + j);
        out[OFF_EIN + 2*t + 1] = (T)((k-1)*PCC + j);
        return;
    }
    t -= M_NS;
    if (t < M_EW){ // east: (k*218+j, k*218+j+1)
        int k = t / 217, j = t % 217;
        int s = k*PCC + j;
        out[OFF_EIE + 2*t]     = (T)s;
        out[OFF_EIE + 2*t + 1] = (T)(s + 1);
        return;
    }
    t -= M_EW;
    if (t < M_NS){ // south: (k*218+j, (k+1)*218+j)
        int k = t / PCC, j = t % PCC;
        int s = k*PCC + j;
        out[OFF_EIS + 2*t]     = (T)s;
        out[OFF_EIS + 2*t + 1] = (T)(s + PCC);
        return;
    }
    t -= M_NS;
    if (t < M_EW){ // west: (k*218+j, k*218+j-1), j=1..217
        int k = t / 217, j = t % 217 + 1;
        int s = k*PCC + j;
        out[OFF_EIW + 2*t]     = (T)s;
        out[OFF_EIW + 2*t + 1] = (T)(s - 1);
        return;
    }
}

// =====================================================================
// Pooled edge features: max over the 2 (or 1) contributing original edges
// =====================================================================
template<typename T>
__global__ void k_efeat(T* __restrict__ out){
    const int d = blockIdx.y;
    const int M = (d == 0 || d == 2) ? M_NS : M_EW;
    int t = blockIdx.x * 256 + threadIdx.x;
    if (t >= M * 8) return;
    int m = t >> 3, fi = (t & 7) * 4;
    int e1, stride2 = 1; bool two = true; size_t off;
    if (d == 0){      int k = 1 + m/PCC, j = m%PCC; e1 = (2*k - 1)*WW + 2*j;      off = OFF_FN; }
    else if (d == 1){ int k = m/217,     j = m%217; e1 = 2*k*(WW-1) + 2*j + 1;    stride2 = WW-1; two = (k < 247); off = OFF_FE; }
    else if (d == 2){ int k = m/PCC,     j = m%PCC; e1 = (2*k + 1)*WW + 2*j;      off = OFF_FS; }
    else {            int k = m/217,     j = m%217 + 1; e1 = 2*k*(WW-1) + 2*j - 1; stride2 = WW-1; two = (k < 247); off = OFF_FW; }
    const float* ED = &g_EDGE[d][0];
    float4 a = *(const float4*)(ED + (size_t)e1*32 + fi);
    if (two){
        float4 b = *(const float4*)(ED + (size_t)(e1 + stride2)*32 + fi);
        a.x = fmaxf(a.x, b.x); a.y = fmaxf(a.y, b.y);
        a.z = fmaxf(a.z, b.z); a.w = fmaxf(a.w, b.w);
    }
    T* o = out + off + (size_t)m*32 + fi;
    o[0] = (T)a.x; o[1] = (T)a.y; o[2] = (T)a.z; o[3] = (T)a.w;
}

// =====================================================================
extern "C" void kernel_launch(void* const* d_in, const int* in_sizes, int n_in,
                              void* d_out, int out_size){
    const float* x     = (const float*)d_in[0];
    // d_in[1..5]: node_loc + edge indices — regular grid, closed-form, unused
    const float* efN   = (const float*)d_in[6];
    const float* efE   = (const float*)d_in[7];
    const float* efS   = (const float*)d_in[8];
    const float* efW   = (const float*)d_in[9];
    const float* Wemb  = (const float*)d_in[10];
    const float* Wedge = (const float*)d_in[11];
    const float* Wnode = (const float*)d_in[12];

    const int gm = (NN + 127) / 128;             // 1687
    k_gemm1<<<gm, 256>>>(x, Wemb);
    dim3 ge((E_NS + 127) / 128, 4);              // 1683 x 4
    k_edge<<<ge, 256>>>(efN, efE, efS, efW, Wedge);
    k_gemm2<<<gm, 256>>>(x, Wnode);

    const int metaT = NP + 2*M_NS + 2*M_EW;      // 269388
    dim3 gf((M_NS*8 + 255) / 256, 4);

    if (out_size == OUT_TOTAL){  // float32 output (expected)
        float* out = (float*)d_out;
        k_pool<float><<<(NP*32 + 255)/256, 256>>>(out);
        k_meta<float><<<(metaT + 255)/256, 256>>>(out);
        k_efeat<float><<<gf, 256>>>(out);
    } else {                     // fallback: float64 output
        double* out = (double*)d_out;
        k_pool<double><<<(NP*32 + 255)/256, 256>>>(out);
        k_meta<double><<<(metaT + 255)/256, 256>>>(out);
        k_efeat<double><<<gf, 256>>>(out);
    }
}

// round 4
// speedup vs baseline: 1.3776x; 1.3776x over previous
#include <cuda_runtime.h>
#include <cuda_bf16.h>
#include <cstdint>

// ---------------- static problem constants ----------------
#define HH 495
#define WW 436
#define NN (HH*WW)            // 215820 nodes
#define PRR 248
#define PCC 218
#define NP (PRR*PCC)          // 54064 pooled nodes
#define E_NS ((HH-1)*WW)      // 215384 edges (north & south)
#define E_EW (HH*(WW-1))      // 215325 edges (east & west)
#define M_NS (247*218)
#define M_EW (248*217)

// output layout (float elements)
#define OFF_POS 6920192
#define OFF_EIN 7028320
#define OFF_EIE 7136012
#define OFF_EIS 7243644
#define OFF_EIW 7351336
#define OFF_FN  7458968
#define OFF_FE  9182040
#define OFF_FS  10904152
#define OFF_FW  12627224
#define OUT_TOTAL 14349336

#define PAD 132

// ---------------- scratch ----------------
__device__ float g_XQ[(size_t)NN*128];
__device__ float g_EDGE[4][(size_t)E_NS*32];
__device__ float g_X2[(size_t)NN*128];
// preconverted bf16 weight images, layout [n][k] (256B rows) with 16B-chunk swizzle
__device__ __align__(16) __nv_bfloat16 g_B1h[128*128];
__device__ __align__(16) __nv_bfloat16 g_B1l[128*128];
__device__ __align__(16) __nv_bfloat16 g_B2h[2][128*128];
__device__ __align__(16) __nv_bfloat16 g_B2l[2][128*128];

// ---------------- helpers ----------------
__device__ __forceinline__ uint32_t smem_u32(const void* p){
    uint32_t a;
    asm("{ .reg .u64 t; cvta.to.shared.u64 t, %1; cvt.u32.u64 %0, t; }" : "=r"(a) : "l"(p));
    return a;
}
// swizzled byte offset inside a [row][128 bf16] tile (256B rows, 16B chunks XOR row%8)
__device__ __host__ __forceinline__ uint32_t swoff(int row, int k){
    return (uint32_t)(row * 256 + (((k >> 3) ^ (row & 7)) << 4) + (k & 7) * 2);
}
// bf16 hi/lo split of 2 floats -> packed bf16x2 words
__device__ __forceinline__ void split2(float a, float b, uint32_t &h, uint32_t &l){
    float ah = __bfloat162float(__float2bfloat16_rn(a));
    float bh = __bfloat162float(__float2bfloat16_rn(b));
    __nv_bfloat162 H = __floats2bfloat162_rn(ah, bh);
    __nv_bfloat162 L = __floats2bfloat162_rn(a - ah, b - bh);
    h = *reinterpret_cast<uint32_t*>(&H);
    l = *reinterpret_cast<uint32_t*>(&L);
}

#define LDSM_X4(r0,r1,r2,r3,addr) \
    asm volatile("ldmatrix.sync.aligned.m8n8.x4.shared.b16 {%0,%1,%2,%3}, [%4];" \
        : "=r"(r0), "=r"(r1), "=r"(r2), "=r"(r3) : "r"(addr))

__device__ __forceinline__ void mma_bf16(float* c, const uint32_t* a, uint32_t b0, uint32_t b1){
    asm volatile(
        "mma.sync.aligned.m16n8k16.row.col.f32.bf16.bf16.f32 "
        "{%0,%1,%2,%3}, {%4,%5,%6,%7}, {%8,%9}, {%0,%1,%2,%3};"
        : "+f"(c[0]), "+f"(c[1]), "+f"(c[2]), "+f"(c[3])
        : "r"(a[0]), "r"(a[1]), "r"(a[2]), "r"(a[3]), "r"(b0), "r"(b1));
}

// dynamic smem layout (bytes)
#define SOF_AH 0
#define SOF_AL 32768
#define SOF_BH 65536
#define SOF_BL 98304
#define SMEM_TG 131072

// ---------------- weight preconversion ----------------
__global__ void k_conv_w(const float* __restrict__ Wemb, const float* __restrict__ Wnode){
    int t = blockIdx.x * 256 + threadIdx.x;
    if (t < 16384){
        int n = t >> 7, k = t & 127;
        float w = Wemb[(n >> 5) * 4096 + k * 32 + (n & 31)];
        float wh = __bfloat162float(__float2bfloat16_rn(w));
        uint32_t s = swoff(n, k);
        *(__nv_bfloat16*)((char*)g_B1h + s) = __float2bfloat16_rn(wh);
        *(__nv_bfloat16*)((char*)g_B1l + s) = __float2bfloat16_rn(w - wh);
        return;
    }
    t -= 16384;
    if (t < 32768){
        int c = t >> 14, r = t & 16383;
        int n = r >> 7, k = r & 127;
        float w = Wnode[(c * 128 + k) * 128 + n];
        if (c) w *= 0.25f;
        float wh = __bfloat162float(__float2bfloat16_rn(w));
        uint32_t s = swoff(n, k);
        *(__nv_bfloat16*)((char*)g_B2h[c] + s) = __float2bfloat16_rn(wh);
        *(__nv_bfloat16*)((char*)g_B2l[c] + s) = __float2bfloat16_rn(w - wh);
    }
}

// ---------------- shared mma core: 3-pass split over one 128-K chunk ----------------
// acc[2][8][4]: warp tile 32(m) x 64(n)
__device__ __forceinline__ void mma_chunk(char* smem, uint32_t sb, int warp_m, int warp_n,
                                          int lane, float acc[2][8][4]){
#pragma unroll
    for (int pass = 0; pass < 3; pass++){
        uint32_t Ab = sb + ((pass == 1) ? SOF_AL : SOF_AH);
        uint32_t Bb = sb + ((pass == 2) ? SOF_BL : SOF_BH);
#pragma unroll
        for (int kc = 0; kc < 8; kc++){
            uint32_t a[2][4];
#pragma unroll
            for (int tfrag = 0; tfrag < 2; tfrag++){
                int row = warp_m * 32 + tfrag * 16 + (lane & 15);
                int chunk = kc * 2 + (lane >> 4);
                uint32_t addr = Ab + row * 256 + (((chunk ^ (row & 7)) << 4));
                LDSM_X4(a[tfrag][0], a[tfrag][1], a[tfrag][2], a[tfrag][3], addr);
            }
            uint32_t bfr[8][2];
#pragma unroll
            for (int jj = 0; jj < 4; jj++){
                int rowN = warp_n * 64 + jj * 16 + (lane & 7) + ((lane >> 4) << 3);
                int chunk = kc * 2 + ((lane >> 3) & 1);
                uint32_t addr = Bb + rowN * 256 + (((chunk ^ (rowN & 7)) << 4));
                uint32_t r0, r1, r2, r3;
                LDSM_X4(r0, r1, r2, r3, addr);
                bfr[jj*2][0] = r0;   bfr[jj*2][1] = r1;
                bfr[jj*2+1][0] = r2; bfr[jj*2+1][1] = r3;
            }
#pragma unroll
            for (int tfrag = 0; tfrag < 2; tfrag++)
#pragma unroll
                for (int j = 0; j < 8; j++)
                    mma_bf16(acc[tfrag][j], a[tfrag], bfr[j][0], bfr[j][1]);
        }
    }
}

__device__ __forceinline__ void epilogue_store(float* __restrict__ dst, int M0, int warp_m,
                                               int warp_n, int lane, float acc[2][8][4]){
#pragma unroll
    for (int tfrag = 0; tfrag < 2; tfrag++){
        int r0 = M0 + warp_m * 32 + tfrag * 16 + (lane >> 2);
#pragma unroll
        for (int j = 0; j < 8; j++){
            int col = warp_n * 64 + j * 8 + (lane & 3) * 2;
            if (r0 < NN)
                *(float2*)(dst + (size_t)r0 * 128 + col) =
                    make_float2(fmaxf(acc[tfrag][j][0], 0.f), fmaxf(acc[tfrag][j][1], 0.f));
            if (r0 + 8 < NN)
                *(float2*)(dst + (size_t)(r0 + 8) * 128 + col) =
                    make_float2(fmaxf(acc[tfrag][j][2], 0.f), fmaxf(acc[tfrag][j][3], 0.f));
        }
    }
}

// ---------------- GEMM1: XQ = relu(x @ Wcat) via HMMA ----------------
__global__ __launch_bounds__(256) void k_tg1(const float* __restrict__ x){
    extern __shared__ char smem[];
    const uint32_t sb = smem_u32(smem);
    const int tid = threadIdx.x, wid = tid >> 5, lane = tid & 31;
    const int warp_m = wid >> 1, warp_n = wid & 1;
    const int M0 = blockIdx.x * 128;

    // fill A hi/lo: thread handles (row, k8-chunk)
#pragma unroll
    for (int i = 0; i < 8; i++){
        int lin = tid + 256 * i;
        int m = lin >> 4, k8 = (lin & 15) * 8;
        float4 v0 = make_float4(0.f,0.f,0.f,0.f), v1 = v0;
        if (M0 + m < NN){
            const float* src = x + (size_t)(M0 + m) * 128 + k8;
            v0 = *(const float4*)(src);
            v1 = *(const float4*)(src + 4);
        }
        uint4 H, L;
        split2(v0.x, v0.y, H.x, L.x); split2(v0.z, v0.w, H.y, L.y);
        split2(v1.x, v1.y, H.z, L.z); split2(v1.z, v1.w, H.w, L.w);
        uint32_t s = swoff(m, k8);
        *(uint4*)(smem + SOF_AH + s) = H;
        *(uint4*)(smem + SOF_AL + s) = L;
    }
    // copy B images (32KB each)
    {
        const uint4* bh = (const uint4*)g_B1h;
        const uint4* bl = (const uint4*)g_B1l;
#pragma unroll
        for (int i = 0; i < 8; i++){
            int idx = tid + 256 * i;
            ((uint4*)(smem + SOF_BH))[idx] = bh[idx];
            ((uint4*)(smem + SOF_BL))[idx] = bl[idx];
        }
    }
    __syncthreads();

    float acc[2][8][4];
#pragma unroll
    for (int t = 0; t < 2; t++)
#pragma unroll
        for (int j = 0; j < 8; j++)
#pragma unroll
            for (int e = 0; e < 4; e++) acc[t][j][e] = 0.f;

    mma_chunk(smem, sb, warp_m, warp_n, lane, acc);
    epilogue_store(g_XQ, M0, warp_m, warp_n, lane, acc);
}

// ---------------- GEMM2: X2 = relu([x | aggs] @ Wnode') via HMMA ----------------
__global__ __launch_bounds__(256) void k_tg2(const float* __restrict__ x){
    extern __shared__ char smem[];
    const uint32_t sb = smem_u32(smem);
    const int tid = threadIdx.x, wid = tid >> 5, lane = tid & 31;
    const int warp_m = wid >> 1, warp_n = wid & 1;
    const int M0 = blockIdx.x * 128;

    float acc[2][8][4];
#pragma unroll
    for (int t = 0; t < 2; t++)
#pragma unroll
        for (int j = 0; j < 8; j++)
#pragma unroll
            for (int e = 0; e < 4; e++) acc[t][j][e] = 0.f;

    for (int chunk = 0; chunk < 2; chunk++){
        if (chunk == 1) __syncthreads();   // mma reads done before refill
        // fill A for this K-chunk
#pragma unroll
        for (int i = 0; i < 8; i++){
            int lin = tid + 256 * i;
            int m = lin >> 4, k8 = (lin & 15) * 8;
            int gm = M0 + m;
            float4 v0 = make_float4(0.f,0.f,0.f,0.f), v1 = v0;
            if (gm < NN){
                if (chunk == 0){
                    const float* src = x + (size_t)gm * 128 + k8;
                    v0 = *(const float4*)(src);
                    v1 = *(const float4*)(src + 4);
                } else {
                    int d = k8 >> 5, u = k8 & 31;
                    int r = gm / WW, c = gm - r * WW;
                    int e = -1;
                    if (d == 0){ if (r < HH-1) e = gm; }
                    else if (d == 1){ if (c >= 1) e = r*(WW-1) + c - 1; }
                    else if (d == 2){ if (r >= 1) e = gm - WW; }
                    else            { if (c <= WW-2) e = r*(WW-1) + c; }
                    if (e >= 0){
                        const float* src = &g_EDGE[d][0] + (size_t)e * 32 + u;
                        v0 = *(const float4*)(src);
                        v1 = *(const float4*)(src + 4);
                    }
                }
            }
            uint4 H, L;
            split2(v0.x, v0.y, H.x, L.x); split2(v0.z, v0.w, H.y, L.y);
            split2(v1.x, v1.y, H.z, L.z); split2(v1.z, v1.w, H.w, L.w);
            uint32_t s = swoff(m, k8);
            *(uint4*)(smem + SOF_AH + s) = H;
            *(uint4*)(smem + SOF_AL + s) = L;
        }
        {
            const uint4* bh = (const uint4*)g_B2h[chunk];
            const uint4* bl = (const uint4*)g_B2l[chunk];
#pragma unroll
            for (int i = 0; i < 8; i++){
                int idx = tid + 256 * i;
                ((uint4*)(smem + SOF_BH))[idx] = bh[idx];
                ((uint4*)(smem + SOF_BL))[idx] = bl[idx];
            }
        }
        __syncthreads();
        mma_chunk(smem, sb, warp_m, warp_n, lane, acc);
    }
    epilogue_store(g_X2, M0, warp_m, warp_n, lane, acc);
}

// ---------------- FFMA2 helpers (edge kernel) ----------------
__device__ __forceinline__ unsigned long long pk2(float x, float y){
    unsigned long long r;
    asm("mov.b64 %0, {%1,%2};" : "=l"(r) : "f"(x), "f"(y));
    return r;
}
__device__ __forceinline__ void upk(unsigned long long v, float &x, float &y){
    asm("mov.b64 {%0,%1}, %2;" : "=f"(x), "=f"(y) : "l"(v));
}
__device__ __forceinline__ void ffma2(unsigned long long &d, unsigned long long a, unsigned long long b){
    asm("fma.rn.f32x2 %0, %1, %2, %0;" : "+l"(d) : "l"(a), "l"(b));
}

// =====================================================================
// Edge GEMM (FFMA2, known-good from R2)
// =====================================================================
__global__ __launch_bounds__(256) void k_edge(const float* __restrict__ efN,
                                              const float* __restrict__ efE,
                                              const float* __restrict__ efS,
                                              const float* __restrict__ efW,
                                              const float* __restrict__ Wedge){
    const int q = blockIdx.y;
    const float* ef = (q==0) ? efN : (q==1) ? efE : (q==2) ? efS : efW;
    const int E = (q==0 || q==2) ? E_NS : E_EW;
    const int M0 = blockIdx.x * 128;
    if (M0 >= E) return;

    __shared__ float As[32*PAD];
    __shared__ float Bs[32*32];
    const int tid = threadIdx.x;
    const int tx = tid & 7, ty = tid >> 3;

    unsigned long long acc[4][2];
#pragma unroll
    for (int i = 0; i < 4; i++){ acc[i][0] = 0ull; acc[i][1] = 0ull; }

    for (int kc = 0; kc < 3; kc++){
#pragma unroll
        for (int i = 0; i < 4; i++){
            int lin = tid + 256*i;
            int m = lin >> 3, k4 = (lin & 7) * 4;
            int e = M0 + m;
            float4 v = make_float4(0.f,0.f,0.f,0.f);
            if (e < E){
                if (kc == 0){
                    v = *(const float4*)(ef + (size_t)e*32 + k4);
                } else {
                    int s, t;
                    if (q == 0){ int r = 1 + e/WW,     c = e%WW;         s = r*WW + c; t = s - WW; }
                    else if (q == 1){ int r = e/(WW-1), c = e%(WW-1);    s = r*WW + c; t = s + 1;  }
                    else if (q == 2){ int r = e/WW,     c = e%WW;        s = r*WW + c; t = s + WW; }
                    else            { int r = e/(WW-1), c = e%(WW-1)+1;  s = r*WW + c; t = s - 1;  }
                    int node = (kc == 1) ? s : t;
                    v = *(const float4*)(g_XQ + (size_t)node*128 + q*32 + k4);
                }
            }
            As[(k4+0)*PAD + m] = v.x;
            As[(k4+1)*PAD + m] = v.y;
            As[(k4+2)*PAD + m] = v.z;
            As[(k4+3)*PAD + m] = v.w;
        }
        {
            int k = tid >> 3, j = (tid & 7) * 4;
            *(float4*)(Bs + k*32 + j) = *(const float4*)(Wedge + q*3072 + (kc*32 + k)*32 + j);
        }
        __syncthreads();
#pragma unroll
        for (int k = 0; k < 32; k++){
            float4 a = *(const float4*)(As + k*PAD + ty*4);
            ulonglong2 b = *(const ulonglong2*)(Bs + k*32 + tx*4);
            unsigned long long ad0 = pk2(a.x,a.x), ad1 = pk2(a.y,a.y),
                               ad2 = pk2(a.z,a.z), ad3 = pk2(a.w,a.w);
            ffma2(acc[0][0], ad0, b.x); ffma2(acc[0][1], ad0, b.y);
            ffma2(acc[1][0], ad1, b.x); ffma2(acc[1][1], ad1, b.y);
            ffma2(acc[2][0], ad2, b.x); ffma2(acc[2][1], ad2, b.y);
            ffma2(acc[3][0], ad3, b.x); ffma2(acc[3][1], ad3, b.y);
        }
        __syncthreads();
    }
    float* ED = &g_EDGE[q][0];
#pragma unroll
    for (int i = 0; i < 4; i++){
        int e = M0 + ty*4 + i;
        if (e >= E) break;
        float o0,o1,o2,o3;
        upk(acc[i][0], o0, o1); upk(acc[i][1], o2, o3);
        *(float4*)(ED + (size_t)e*32 + tx*4) =
            make_float4(fmaxf(o0,0.f), fmaxf(o1,0.f), fmaxf(o2,0.f), fmaxf(o3,0.f));
    }
}

// ---------------- pooling / metadata / edge-feature kernels (unchanged) ----------------
template<typename T>
__global__ void k_pool(T* __restrict__ out){
    int t = blockIdx.x * 256 + threadIdx.x;
    if (t >= NP * 32) return;
    int p = t >> 5, fi = (t & 31) * 4;
    int pr = p / PCC, pc = p % PCC;
    int n00 = (2*pr)*WW + 2*pc;
    const float* base = g_X2 + (size_t)n00*128 + fi;
    float4 a = *(const float4*)(base);
    float4 b = *(const float4*)(base + 128);
    a.x = fmaxf(a.x, b.x); a.y = fmaxf(a.y, b.y);
    a.z = fmaxf(a.z, b.z); a.w = fmaxf(a.w, b.w);
    if (2*pr + 1 < HH){
        float4 c4 = *(const float4*)(base + (size_t)128*WW);
        float4 d4 = *(const float4*)(base + (size_t)128*WW + 128);
        a.x = fmaxf(a.x, fmaxf(c4.x, d4.x));
        a.y = fmaxf(a.y, fmaxf(c4.y, d4.y));
        a.z = fmaxf(a.z, fmaxf(c4.z, d4.z));
        a.w = fmaxf(a.w, fmaxf(c4.w, d4.w));
    }
    T* o = out + (size_t)p*128 + fi;
    o[0] = (T)a.x; o[1] = (T)a.y; o[2] = (T)a.z; o[3] = (T)a.w;
}

template<typename T>
__global__ void k_meta(T* __restrict__ out){
    int t = blockIdx.x * 256 + threadIdx.x;
    if (t < NP){
        out[OFF_POS + 2*t]     = (T)(t / PCC);
        out[OFF_POS + 2*t + 1] = (T)(t % PCC);
        return;
    }
    t -= NP;
    if (t < M_NS){
        int k = 1 + t / PCC, j = t % PCC;
        out[OFF_EIN + 2*t]     = (T)(k*PCC + j);
        out[OFF_EIN + 2*t + 1] = (T)((k-1)*PCC + j);
        return;
    }
    t -= M_NS;
    if (t < M_EW){
        int k = t / 217, j = t % 217;
        int s = k*PCC + j;
        out[OFF_EIE + 2*t]     = (T)s;
        out[OFF_EIE + 2*t + 1] = (T)(s + 1);
        return;
    }
    t -= M_EW;
    if (t < M_NS){
        int k = t / PCC, j = t % PCC;
        int s = k*PCC + j;
        out[OFF_EIS + 2*t]     = (T)s;
        out[OFF_EIS + 2*t + 1] = (T)(s + PCC);
        return;
    }
    t -= M_NS;
    if (t < M_EW){
        int k = t / 217, j = t % 217 + 1;
        int s = k*PCC + j;
        out[OFF_EIW + 2*t]     = (T)s;
        out[OFF_EIW + 2*t + 1] = (T)(s - 1);
        return;
    }
}

template<typename T>
__global__ void k_efeat(T* __restrict__ out){
    const int d = blockIdx.y;
    const int M = (d == 0 || d == 2) ? M_NS : M_EW;
    int t = blockIdx.x * 256 + threadIdx.x;
    if (t >= M * 8) return;
    int m = t >> 3, fi = (t & 7) * 4;
    int e1, stride2 = 1; bool two = true; size_t off;
    if (d == 0){      int k = 1 + m/PCC, j = m%PCC; e1 = (2*k - 1)*WW + 2*j;      off = OFF_FN; }
    else if (d == 1){ int k = m/217,     j = m%217; e1 = 2*k*(WW-1) + 2*j + 1;    stride2 = WW-1; two = (k < 247); off = OFF_FE; }
    else if (d == 2){ int k = m/PCC,     j = m%PCC; e1 = (2*k + 1)*WW + 2*j;      off = OFF_FS; }
    else {            int k = m/217,     j = m%217 + 1; e1 = 2*k*(WW-1) + 2*j - 1; stride2 = WW-1; two = (k < 247); off = OFF_FW; }
    const float* ED = &g_EDGE[d][0];
    float4 a = *(const float4*)(ED + (size_t)e1*32 + fi);
    if (two){
        float4 b = *(const float4*)(ED + (size_t)(e1 + stride2)*32 + fi);
        a.x = fmaxf(a.x, b.x); a.y = fmaxf(a.y, b.y);
        a.z = fmaxf(a.z, b.z); a.w = fmaxf(a.w, b.w);
    }
    T* o = out + off + (size_t)m*32 + fi;
    o[0] = (T)a.x; o[1] = (T)a.y; o[2] = (T)a.z; o[3] = (T)a.w;
}

// =====================================================================
extern "C" void kernel_launch(void* const* d_in, const int* in_sizes, int n_in,
                              void* d_out, int out_size){
    const float* x     = (const float*)d_in[0];
    const float* efN   = (const float*)d_in[6];
    const float* efE   = (const float*)d_in[7];
    const float* efS   = (const float*)d_in[8];
    const float* efW   = (const float*)d_in[9];
    const float* Wemb  = (const float*)d_in[10];
    const float* Wedge = (const float*)d_in[11];
    const float* Wnode = (const float*)d_in[12];

    static bool attr_done = false;
    if (!attr_done){
        cudaFuncSetAttribute(k_tg1, cudaFuncAttributeMaxDynamicSharedMemorySize, SMEM_TG);
        cudaFuncSetAttribute(k_tg2, cudaFuncAttributeMaxDynamicSharedMemorySize, SMEM_TG);
        attr_done = true;
    }

    const int gm = (NN + 127) / 128;             // 1687 tiles
    k_conv_w<<<(49152 + 255)/256, 256>>>(Wemb, Wnode);
    k_tg1<<<gm, 256, SMEM_TG>>>(x);
    dim3 ge((E_NS + 127) / 128, 4);
    k_edge<<<ge, 256>>>(efN, efE, efS, efW, Wedge);
    k_tg2<<<gm, 256, SMEM_TG>>>(x);

    const int metaT = NP + 2*M_NS + 2*M_EW;
    dim3 gf((M_NS*8 + 255) / 256, 4);

    if (out_size == OUT_TOTAL){
        float* out = (float*)d_out;
        k_pool<float><<<(NP*32 + 255)/256, 256>>>(out);
        k_meta<float><<<(metaT + 255)/256, 256>>>(out);
        k_efeat<float><<<gf, 256>>>(out);
    } else {
        double* out = (double*)d_out;
        k_pool<double><<<(NP*32 + 255)/256, 256>>>(out);
        k_meta<double><<<(metaT + 255)/256, 256>>>(out);
        k_efeat<double><<<gf, 256>>>(out);
    }
}

// round 6
// speedup vs baseline: 1.4810x; 1.0750x over previous
#include <cuda_runtime.h>
#include <cuda_bf16.h>
#include <cstdint>

// ---------------- static problem constants ----------------
#define HH 495
#define WW 436
#define NN (HH*WW)            // 215820 nodes
#define PRR 248
#define PCC 218
#define NP (PRR*PCC)          // 54064 pooled nodes
#define E_NS ((HH-1)*WW)      // 215384 edges (north & south)
#define E_EW (HH*(WW-1))      // 215325 edges (east & west)
#define M_NS (247*218)
#define M_EW (248*217)

// output layout (float elements)
#define OFF_POS 6920192
#define OFF_EIN 7028320
#define OFF_EIE 7136012
#define OFF_EIS 7243644
#define OFF_EIW 7351336
#define OFF_FN  7458968
#define OFF_FE  9182040
#define OFF_FS  10904152
#define OFF_FW  12627224
#define OUT_TOTAL 14349336

// ---------------- scratch ----------------
__device__ float g_XQ[(size_t)NN*128];
__device__ float g_EDGE[4][(size_t)E_NS*32];
__device__ float g_X2[(size_t)NN*128];
// preconverted bf16 weight images, layout [n][k] (256B rows) with 16B-chunk swizzle
__device__ __align__(16) __nv_bfloat16 g_B1h[128*128];
__device__ __align__(16) __nv_bfloat16 g_B1l[128*128];
__device__ __align__(16) __nv_bfloat16 g_B2h[2][128*128];
__device__ __align__(16) __nv_bfloat16 g_B2l[2][128*128];
__device__ __align__(16) __nv_bfloat16 g_BEh[4][32*128];   // edge weights, K padded 96->128
__device__ __align__(16) __nv_bfloat16 g_BEl[4][32*128];

// ---------------- helpers ----------------
__device__ __forceinline__ uint32_t smem_u32(const void* p){
    uint32_t a;
    asm("{ .reg .u64 t; cvta.to.shared.u64 t, %1; cvt.u32.u64 %0, t; }" : "=r"(a) : "l"(p));
    return a;
}
// swizzled byte offset inside a [row][128 bf16] tile (256B rows, 16B chunks XOR row%8)
__device__ __forceinline__ uint32_t swoff(int row, int k){
    return (uint32_t)(row * 256 + (((k >> 3) ^ (row & 7)) << 4) + (k & 7) * 2);
}
// bf16 hi/lo split of 2 floats -> packed bf16x2 words
__device__ __forceinline__ void split2(float a, float b, uint32_t &h, uint32_t &l){
    float ah = __bfloat162float(__float2bfloat16_rn(a));
    float bh = __bfloat162float(__float2bfloat16_rn(b));
    __nv_bfloat162 H = __floats2bfloat162_rn(ah, bh);
    __nv_bfloat162 L = __floats2bfloat162_rn(a - ah, b - bh);
    h = *reinterpret_cast<uint32_t*>(&H);
    l = *reinterpret_cast<uint32_t*>(&L);
}

#define LDSM_X4(r0,r1,r2,r3,addr) \
    asm volatile("ldmatrix.sync.aligned.m8n8.x4.shared.b16 {%0,%1,%2,%3}, [%4];" \
        : "=r"(r0), "=r"(r1), "=r"(r2), "=r"(r3) : "r"(addr))

__device__ __forceinline__ void mma_bf16(float* c, const uint32_t* a, uint32_t b0, uint32_t b1){
    asm volatile(
        "mma.sync.aligned.m16n8k16.row.col.f32.bf16.bf16.f32 "
        "{%0,%1,%2,%3}, {%4,%5,%6,%7}, {%8,%9}, {%0,%1,%2,%3};"
        : "+f"(c[0]), "+f"(c[1]), "+f"(c[2]), "+f"(c[3])
        : "r"(a[0]), "r"(a[1]), "r"(a[2]), "r"(a[3]), "r"(b0), "r"(b1));
}

// dynamic smem layout (bytes) for node GEMMs
#define SOF_AH 0
#define SOF_AL 32768
#define SOF_BH 65536
#define SOF_BL 98304
#define SMEM_TG 131072
// for edge GEMM
#define EOF_AH 0
#define EOF_AL 32768
#define EOF_BH 65536
#define EOF_BL 73728
#define SMEM_TE 81920

// ---------------- weight preconversion ----------------
__global__ void k_conv_w(const float* __restrict__ Wemb, const float* __restrict__ Wnode,
                         const float* __restrict__ Wedge){
    int t = blockIdx.x * 256 + threadIdx.x;
    if (t < 16384){
        int n = t >> 7, k = t & 127;
        float w = Wemb[(n >> 5) * 4096 + k * 32 + (n & 31)];
        float wh = __bfloat162float(__float2bfloat16_rn(w));
        uint32_t s = swoff(n, k);
        *(__nv_bfloat16*)((char*)g_B1h + s) = __float2bfloat16_rn(wh);
        *(__nv_bfloat16*)((char*)g_B1l + s) = __float2bfloat16_rn(w - wh);
        return;
    }
    t -= 16384;
    if (t < 32768){
        int c = t >> 14, r = t & 16383;
        int n = r >> 7, k = r & 127;
        float w = Wnode[(c * 128 + k) * 128 + n];
        if (c) w *= 0.25f;
        float wh = __bfloat162float(__float2bfloat16_rn(w));
        uint32_t s = swoff(n, k);
        *(__nv_bfloat16*)((char*)g_B2h[c] + s) = __float2bfloat16_rn(wh);
        *(__nv_bfloat16*)((char*)g_B2l[c] + s) = __float2bfloat16_rn(w - wh);
        return;
    }
    t -= 32768;
    if (t < 16384){   // edge weights: [4][32n][128k], zero-padded k>=96
        int q = t >> 12, r = t & 4095;
        int n = r >> 7, k = r & 127;
        float w = (k < 96) ? Wedge[q * 3072 + k * 32 + n] : 0.f;
        float wh = __bfloat162float(__float2bfloat16_rn(w));
        uint32_t s = swoff(n, k);
        *(__nv_bfloat16*)((char*)g_BEh[q] + s) = __float2bfloat16_rn(wh);
        *(__nv_bfloat16*)((char*)g_BEl[q] + s) = __float2bfloat16_rn(w - wh);
    }
}

// ---------------- mma core: 3-pass split, warp tile 32m x 32n ----------------
// acc[2][4][4]
__device__ __forceinline__ void mma_chunk16(uint32_t sb, int warp_m, int warp_n,
                                            int lane, float acc[2][4][4]){
#pragma unroll
    for (int pass = 0; pass < 3; pass++){
        uint32_t Ab = sb + ((pass == 1) ? SOF_AL : SOF_AH);
        uint32_t Bb = sb + ((pass == 2) ? SOF_BL : SOF_BH);
#pragma unroll
        for (int kc = 0; kc < 8; kc++){
            uint32_t a[2][4];
#pragma unroll
            for (int tf = 0; tf < 2; tf++){
                int row = warp_m * 32 + tf * 16 + (lane & 15);
                int chunk = kc * 2 + (lane >> 4);
                uint32_t addr = Ab + row * 256 + ((chunk ^ (row & 7)) << 4);
                LDSM_X4(a[tf][0], a[tf][1], a[tf][2], a[tf][3], addr);
            }
            uint32_t bfr[4][2];
#pragma unroll
            for (int jj = 0; jj < 2; jj++){
                int rowN = warp_n * 32 + jj * 16 + (lane & 7) + ((lane >> 4) << 3);
                int chunk = kc * 2 + ((lane >> 3) & 1);
                uint32_t addr = Bb + rowN * 256 + ((chunk ^ (rowN & 7)) << 4);
                uint32_t r0, r1, r2, r3;
                LDSM_X4(r0, r1, r2, r3, addr);
                bfr[jj*2][0] = r0;   bfr[jj*2][1] = r1;
                bfr[jj*2+1][0] = r2; bfr[jj*2+1][1] = r3;
            }
#pragma unroll
            for (int tf = 0; tf < 2; tf++)
#pragma unroll
                for (int j = 0; j < 4; j++)
                    mma_bf16(acc[tf][j], a[tf], bfr[j][0], bfr[j][1]);
        }
    }
}

__device__ __forceinline__ void epilogue32(float* __restrict__ dst, int M0, int warp_m,
                                           int warp_n, int lane, float acc[2][4][4]){
#pragma unroll
    for (int tf = 0; tf < 2; tf++){
        int r0 = M0 + warp_m * 32 + tf * 16 + (lane >> 2);
#pragma unroll
        for (int j = 0; j < 4; j++){
            int col = warp_n * 32 + j * 8 + (lane & 3) * 2;
            if (r0 < NN)
                *(float2*)(dst + (size_t)r0 * 128 + col) =
                    make_float2(fmaxf(acc[tf][j][0], 0.f), fmaxf(acc[tf][j][1], 0.f));
            if (r0 + 8 < NN)
                *(float2*)(dst + (size_t)(r0 + 8) * 128 + col) =
                    make_float2(fmaxf(acc[tf][j][2], 0.f), fmaxf(acc[tf][j][3], 0.f));
        }
    }
}

// ---------------- GEMM1: XQ = relu(x @ Wcat) ----------------
__global__ __launch_bounds__(512, 1) void k_tg1(const float* __restrict__ x){
    extern __shared__ char smem[];
    const uint32_t sb = smem_u32(smem);
    const int tid = threadIdx.x, wid = tid >> 5, lane = tid & 31;
    const int warp_m = wid >> 2, warp_n = wid & 3;
    const int M0 = blockIdx.x * 128;

#pragma unroll
    for (int i = 0; i < 4; i++){
        int lin = tid + 512 * i;
        int m = lin >> 4, k8 = (lin & 15) * 8;
        float4 v0 = make_float4(0.f,0.f,0.f,0.f), v1 = v0;
        if (M0 + m < NN){
            const float* src = x + (size_t)(M0 + m) * 128 + k8;
            v0 = *(const float4*)(src);
            v1 = *(const float4*)(src + 4);
        }
        uint4 H, L;
        split2(v0.x, v0.y, H.x, L.x); split2(v0.z, v0.w, H.y, L.y);
        split2(v1.x, v1.y, H.z, L.z); split2(v1.z, v1.w, H.w, L.w);
        uint32_t s = swoff(m, k8);
        *(uint4*)(smem + SOF_AH + s) = H;
        *(uint4*)(smem + SOF_AL + s) = L;
    }
    {
        const uint4* bh = (const uint4*)g_B1h;
        const uint4* bl = (const uint4*)g_B1l;
#pragma unroll
        for (int i = 0; i < 4; i++){
            int idx = tid + 512 * i;
            ((uint4*)(smem + SOF_BH))[idx] = bh[idx];
            ((uint4*)(smem + SOF_BL))[idx] = bl[idx];
        }
    }
    __syncthreads();

    float acc[2][4][4];
#pragma unroll
    for (int t = 0; t < 2; t++)
#pragma unroll
        for (int j = 0; j < 4; j++)
#pragma unroll
            for (int e = 0; e < 4; e++) acc[t][j][e] = 0.f;

    mma_chunk16(sb, warp_m, warp_n, lane, acc);
    epilogue32(g_XQ, M0, warp_m, warp_n, lane, acc);
}

// ---------------- GEMM2: X2 = relu([x | aggs] @ Wnode') ----------------
__global__ __launch_bounds__(512, 1) void k_tg2(const float* __restrict__ x){
    extern __shared__ char smem[];
    const uint32_t sb = smem_u32(smem);
    const int tid = threadIdx.x, wid = tid >> 5, lane = tid & 31;
    const int warp_m = wid >> 2, warp_n = wid & 3;
    const int M0 = blockIdx.x * 128;

    float acc[2][4][4];
#pragma unroll
    for (int t = 0; t < 2; t++)
#pragma unroll
        for (int j = 0; j < 4; j++)
#pragma unroll
            for (int e = 0; e < 4; e++) acc[t][j][e] = 0.f;

    for (int chunk = 0; chunk < 2; chunk++){
        if (chunk == 1) __syncthreads();
#pragma unroll
        for (int i = 0; i < 4; i++){
            int lin = tid + 512 * i;
            int m = lin >> 4, k8 = (lin & 15) * 8;
            int gm = M0 + m;
            float4 v0 = make_float4(0.f,0.f,0.f,0.f), v1 = v0;
            if (gm < NN){
                if (chunk == 0){
                    const float* src = x + (size_t)gm * 128 + k8;
                    v0 = *(const float4*)(src);
                    v1 = *(const float4*)(src + 4);
                } else {
                    int d = k8 >> 5, u = k8 & 31;
                    int r = gm / WW, c = gm - r * WW;
                    int e = -1;
                    if (d == 0){ if (r < HH-1) e = gm; }
                    else if (d == 1){ if (c >= 1) e = r*(WW-1) + c - 1; }
                    else if (d == 2){ if (r >= 1) e = gm - WW; }
                    else            { if (c <= WW-2) e = r*(WW-1) + c; }
                    if (e >= 0){
                        const float* src = &g_EDGE[d][0] + (size_t)e * 32 + u;
                        v0 = *(const float4*)(src);
                        v1 = *(const float4*)(src + 4);
                    }
                }
            }
            uint4 H, L;
            split2(v0.x, v0.y, H.x, L.x); split2(v0.z, v0.w, H.y, L.y);
            split2(v1.x, v1.y, H.z, L.z); split2(v1.z, v1.w, H.w, L.w);
            uint32_t s = swoff(m, k8);
            *(uint4*)(smem + SOF_AH + s) = H;
            *(uint4*)(smem + SOF_AL + s) = L;
        }
        {
            const uint4* bh = (const uint4*)g_B2h[chunk];
            const uint4* bl = (const uint4*)g_B2l[chunk];
#pragma unroll
            for (int i = 0; i < 4; i++){
                int idx = tid + 512 * i;
                ((uint4*)(smem + SOF_BH))[idx] = bh[idx];
                ((uint4*)(smem + SOF_BL))[idx] = bl[idx];
            }
        }
        __syncthreads();
        mma_chunk16(sb, warp_m, warp_n, lane, acc);
    }
    epilogue32(g_X2, M0, warp_m, warp_n, lane, acc);
}

// =====================================================================
// Edge GEMM via HMMA: EDGE[q][e] = relu([ef | XQ[src,q] | XQ[dst,q]] @ W_edge[q])
// block: 128 edges, 256 threads, 8 warps; warp tile 16m x 32n; K=96 (6 kc)
// =====================================================================
__global__ __launch_bounds__(256, 2) void k_edge(const float* __restrict__ efN,
                                                 const float* __restrict__ efE,
                                                 const float* __restrict__ efS,
                                                 const float* __restrict__ efW,
                                                 int unused){
    extern __shared__ char smem[];
    const uint32_t sb = smem_u32(smem);
    const int q = blockIdx.y;
    const float* ef = (q==0) ? efN : (q==1) ? efE : (q==2) ? efS : efW;
    const int E = (q==0 || q==2) ? E_NS : E_EW;
    const int M0 = blockIdx.x * 128;
    if (M0 >= E) return;
    const int tid = threadIdx.x, wid = tid >> 5, lane = tid & 31;

    // fill A: 128 edges x 96 K (12 k8-chunks)
#pragma unroll
    for (int i = 0; i < 6; i++){
        int lin = tid + 256 * i;
        int m = lin / 12, k8c = lin - m * 12;
        int k8 = k8c * 8;
        int e = M0 + m;
        float4 v0 = make_float4(0.f,0.f,0.f,0.f), v1 = v0;
        if (e < E){
            if (k8c < 4){
                const float* src = ef + (size_t)e * 32 + k8;
                v0 = *(const float4*)(src);
                v1 = *(const float4*)(src + 4);
            } else {
                int s, t;
                if (q == 0){ int r = 1 + e/WW,     c = e%WW;         s = r*WW + c; t = s - WW; }
                else if (q == 1){ int r = e/(WW-1), c = e%(WW-1);    s = r*WW + c; t = s + 1;  }
                else if (q == 2){ int r = e/WW,     c = e%WW;        s = r*WW + c; t = s + WW; }
                else            { int r = e/(WW-1), c = e%(WW-1)+1;  s = r*WW + c; t = s - 1;  }
                int node = (k8c < 8) ? s : t;
                int u = (k8c & 3) * 8;
                const float* src = g_XQ + (size_t)node * 128 + q * 32 + u;
                v0 = *(const float4*)(src);
                v1 = *(const float4*)(src + 4);
            }
        }
        uint4 H, L;
        split2(v0.x, v0.y, H.x, L.x); split2(v0.z, v0.w, H.y, L.y);
        split2(v1.x, v1.y, H.z, L.z); split2(v1.z, v1.w, H.w, L.w);
        uint32_t s = swoff(m, k8);
        *(uint4*)(smem + EOF_AH + s) = H;
        *(uint4*)(smem + EOF_AL + s) = L;
    }
    // B images: 8KB each = 512 uint4
    {
        const uint4* bh = (const uint4*)g_BEh[q];
        const uint4* bl = (const uint4*)g_BEl[q];
#pragma unroll
        for (int i = 0; i < 2; i++){
            int idx = tid + 256 * i;
            ((uint4*)(smem + EOF_BH))[idx] = bh[idx];
            ((uint4*)(smem + EOF_BL))[idx] = bl[idx];
        }
    }
    __syncthreads();

    float acc[4][4];
#pragma unroll
    for (int j = 0; j < 4; j++)
#pragma unroll
        for (int e = 0; e < 4; e++) acc[j][e] = 0.f;

#pragma unroll
    for (int pass = 0; pass < 3; pass++){
        uint32_t Ab = sb + ((pass == 1) ? EOF_AL : EOF_AH);
        uint32_t Bb = sb + ((pass == 2) ? EOF_BL : EOF_BH);
#pragma unroll
        for (int kc = 0; kc < 6; kc++){
            uint32_t a[4];
            {
                int row = wid * 16 + (lane & 15);
                int chunk = kc * 2 + (lane >> 4);
                uint32_t addr = Ab + row * 256 + ((chunk ^ (row & 7)) << 4);
                LDSM_X4(a[0], a[1], a[2], a[3], addr);
            }
            uint32_t bfr[4][2];
#pragma unroll
            for (int jj = 0; jj < 2; jj++){
                int rowN = jj * 16 + (lane & 7) + ((lane >> 4) << 3);
                int chunk = kc * 2 + ((lane >> 3) & 1);
                uint32_t addr = Bb + rowN * 256 + ((chunk ^ (rowN & 7)) << 4);
                uint32_t r0, r1, r2, r3;
                LDSM_X4(r0, r1, r2, r3, addr);
                bfr[jj*2][0] = r0;   bfr[jj*2][1] = r1;
                bfr[jj*2+1][0] = r2; bfr[jj*2+1][1] = r3;
            }
#pragma unroll
            for (int j = 0; j < 4; j++)
                mma_bf16(acc[j], a, bfr[j][0], bfr[j][1]);
        }
    }

    float* ED = &g_EDGE[q][0];
    int r0 = M0 + wid * 16 + (lane >> 2);
#pragma unroll
    for (int j = 0; j < 4; j++){
        int col = j * 8 + (lane & 3) * 2;
        if (r0 < E)
            *(float2*)(ED + (size_t)r0 * 32 + col) =
                make_float2(fmaxf(acc[j][0], 0.f), fmaxf(acc[j][1], 0.f));
        if (r0 + 8 < E)
            *(float2*)(ED + (size_t)(r0 + 8) * 32 + col) =
                make_float2(fmaxf(acc[j][2], 0.f), fmaxf(acc[j][3], 0.f));
    }
}

// ---------------- pooling / metadata / edge-feature kernels ----------------
template<typename T>
__global__ void k_pool(T* __restrict__ out){
    int t = blockIdx.x * 256 + threadIdx.x;
    if (t >= NP * 32) return;
    int p = t >> 5, fi = (t & 31) * 4;
    int pr = p / PCC, pc = p % PCC;
    int n00 = (2*pr)*WW + 2*pc;
    const float* base = g_X2 + (size_t)n00*128 + fi;
    float4 a = *(const float4*)(base);
    float4 b = *(const float4*)(base + 128);
    a.x = fmaxf(a.x, b.x); a.y = fmaxf(a.y, b.y);
    a.z = fmaxf(a.z, b.z); a.w = fmaxf(a.w, b.w);
    if (2*pr + 1 < HH){
        float4 c4 = *(const float4*)(base + (size_t)128*WW);
        float4 d4 = *(const float4*)(base + (size_t)128*WW + 128);
        a.x = fmaxf(a.x, fmaxf(c4.x, d4.x));
        a.y = fmaxf(a.y, fmaxf(c4.y, d4.y));
        a.z = fmaxf(a.z, fmaxf(c4.z, d4.z));
        a.w = fmaxf(a.w, fmaxf(c4.w, d4.w));
    }
    T* o = out + (size_t)p*128 + fi;
    o[0] = (T)a.x; o[1] = (T)a.y; o[2] = (T)a.z; o[3] = (T)a.w;
}

template<typename T>
__global__ void k_meta(T* __restrict__ out){
    int t = blockIdx.x * 256 + threadIdx.x;
    if (t < NP){
        out[OFF_POS + 2*t]     = (T)(t / PCC);
        out[OFF_POS + 2*t + 1] = (T)(t % PCC);
        return;
    }
    t -= NP;
    if (t < M_NS){
        int k = 1 + t / PCC, j = t % PCC;
        out[OFF_EIN + 2*t]     = (T)(k*PCC + j);
        out[OFF_EIN + 2*t + 1] = (T)((k-1)*PCC + j);
        return;
    }
    t -= M_NS;
    if (t < M_EW){
        int k = t / 217, j = t % 217;
        int s = k*PCC + j;
        out[OFF_EIE + 2*t]     = (T)s;
        out[OFF_EIE + 2*t + 1] = (T)(s + 1);
        return;
    }
    t -= M_EW;
    if (t < M_NS){
        int k = t / PCC, j = t % PCC;
        int s = k*PCC + j;
        out[OFF_EIS + 2*t]     = (T)s;
        out[OFF_EIS + 2*t + 1] = (T)(s + PCC);
        return;
    }
    t -= M_NS;
    if (t < M_EW){
        int k = t / 217, j = t % 217 + 1;
        int s = k*PCC + j;
        out[OFF_EIW + 2*t]     = (T)s;
        out[OFF_EIW + 2*t + 1] = (T)(s - 1);
        return;
    }
}

template<typename T>
__global__ void k_efeat(T* __restrict__ out){
    const int d = blockIdx.y;
    const int M = (d == 0 || d == 2) ? M_NS : M_EW;
    int t = blockIdx.x * 256 + threadIdx.x;
    if (t >= M * 8) return;
    int m = t >> 3, fi = (t & 7) * 4;
    int e1, stride2 = 1; bool two = true; size_t off;
    if (d == 0){      int k = 1 + m/PCC, j = m%PCC; e1 = (2*k - 1)*WW + 2*j;      off = OFF_FN; }
    else if (d == 1){ int k = m/217,     j = m%217; e1 = 2*k*(WW-1) + 2*j + 1;    stride2 = WW-1; two = (k < 247); off = OFF_FE; }
    else if (d == 2){ int k = m/PCC,     j = m%PCC; e1 = (2*k + 1)*WW + 2*j;      off = OFF_FS; }
    else {            int k = m/217,     j = m%217 + 1; e1 = 2*k*(WW-1) + 2*j - 1; stride2 = WW-1; two = (k < 247); off = OFF_FW; }
    const float* ED = &g_EDGE[d][0];
    float4 a = *(const float4*)(ED + (size_t)e1*32 + fi);
    if (two){
        float4 b = *(const float4*)(ED + (size_t)(e1 + stride2)*32 + fi);
        a.x = fmaxf(a.x, b.x); a.y = fmaxf(a.y, b.y);
        a.z = fmaxf(a.z, b.z); a.w = fmaxf(a.w, b.w);
    }
    T* o = out + off + (size_t)m*32 + fi;
    o[0] = (T)a.x; o[1] = (T)a.y; o[2] = (T)a.z; o[3] = (T)a.w;
}

// =====================================================================
extern "C" void kernel_launch(void* const* d_in, const int* in_sizes, int n_in,
                              void* d_out, int out_size){
    const float* x     = (const float*)d_in[0];
    const float* efN   = (const float*)d_in[6];
    const float* efE   = (const float*)d_in[7];
    const float* efS   = (const float*)d_in[8];
    const float* efW   = (const float*)d_in[9];
    const float* Wemb  = (const float*)d_in[10];
    const float* Wedge = (const float*)d_in[11];
    const float* Wnode = (const float*)d_in[12];

    static bool attr_done = false;
    if (!attr_done){
        cudaFuncSetAttribute(k_tg1, cudaFuncAttributeMaxDynamicSharedMemorySize, SMEM_TG);
        cudaFuncSetAttribute(k_tg2, cudaFuncAttributeMaxDynamicSharedMemorySize, SMEM_TG);
        cudaFuncSetAttribute(k_edge, cudaFuncAttributeMaxDynamicSharedMemorySize, SMEM_TE);
        attr_done = true;
    }

    const int gm = (NN + 127) / 128;             // 1687 tiles
    k_conv_w<<<(65536 + 255)/256, 256>>>(Wemb, Wnode, Wedge);
    k_tg1<<<gm, 512, SMEM_TG>>>(x);
    dim3 ge((E_NS + 127) / 128, 4);
    k_edge<<<ge, 256, SMEM_TE>>>(efN, efE, efS, efW, 0);
    k_tg2<<<gm, 512, SMEM_TG>>>(x);

    const int metaT = NP + 2*M_NS + 2*M_EW;
    dim3 gf((M_NS*8 + 255) / 256, 4);

    if (out_size == OUT_TOTAL){
        float* out = (float*)d_out;
        k_pool<float><<<(NP*32 + 255)/256, 256>>>(out);
        k_meta<float><<<(metaT + 255)/256, 256>>>(out);
        k_efeat<float><<<gf, 256>>>(out);
    } else {
        double* out = (double*)d_out;
        k_pool<double><<<(NP*32 + 255)/256, 256>>>(out);
        k_meta<double><<<(metaT + 255)/256, 256>>>(out);
        k_efeat<double><<<gf, 256>>>(out);
    }
}

// round 7
// speedup vs baseline: 1.9330x; 1.3052x over previous
#include <cuda_runtime.h>
#include <cuda_bf16.h>
#include <cstdint>

// ---------------- static problem constants ----------------
#define HH 495
#define WW 436
#define NN (HH*WW)            // 215820 nodes
#define PRR 248
#define PCC 218
#define NP (PRR*PCC)          // 54064 pooled nodes
#define E_NS ((HH-1)*WW)      // 215384 edges (north & south)
#define E_EW (HH*(WW-1))      // 215325 edges (east & west)
#define M_NS (247*218)
#define M_EW (248*217)

// output layout (float elements)
#define OFF_POS 6920192
#define OFF_EIN 7028320
#define OFF_EIE 7136012
#define OFF_EIS 7243644
#define OFF_EIW 7351336
#define OFF_FN  7458968
#define OFF_FE  9182040
#define OFF_FS  10904152
#define OFF_FW  12627224
#define OUT_TOTAL 14349336

// ---------------- scratch ----------------
__device__ float g_XQ[(size_t)NN*128];
__device__ float g_EDGE[4][(size_t)E_NS*32];
__device__ float g_X2[(size_t)NN*128];
// bf16 weight images in 64-k chunk layout: [chunk][128n][64k], 128B rows, swizzled
__device__ __align__(16) __nv_bfloat16 g_B1h[2][128*64];
__device__ __align__(16) __nv_bfloat16 g_B1l[2][128*64];
__device__ __align__(16) __nv_bfloat16 g_B2h[4][128*64];
__device__ __align__(16) __nv_bfloat16 g_B2l[4][128*64];
// edge weights keep 128-k rows (256B), K padded 96->128
__device__ __align__(16) __nv_bfloat16 g_BEh[4][32*128];
__device__ __align__(16) __nv_bfloat16 g_BEl[4][32*128];

// ---------------- helpers ----------------
__device__ __forceinline__ uint32_t smem_u32(const void* p){
    uint32_t a;
    asm("{ .reg .u64 t; cvta.to.shared.u64 t, %1; cvt.u32.u64 %0, t; }" : "=r"(a) : "l"(p));
    return a;
}
// swizzled byte offset, 64-k rows (128B): 8 chunks of 16B XOR row%8
__device__ __forceinline__ uint32_t swoff64(int row, int k){
    return (uint32_t)(row * 128 + (((k >> 3) ^ (row & 7)) << 4) + (k & 7) * 2);
}
// swizzled byte offset, 128-k rows (256B)
__device__ __forceinline__ uint32_t swoff256(int row, int k){
    return (uint32_t)(row * 256 + (((k >> 3) ^ (row & 7)) << 4) + (k & 7) * 2);
}
__device__ __forceinline__ void split2(float a, float b, uint32_t &h, uint32_t &l){
    float ah = __bfloat162float(__float2bfloat16_rn(a));
    float bh = __bfloat162float(__float2bfloat16_rn(b));
    __nv_bfloat162 H = __floats2bfloat162_rn(ah, bh);
    __nv_bfloat162 L = __floats2bfloat162_rn(a - ah, b - bh);
    h = *reinterpret_cast<uint32_t*>(&H);
    l = *reinterpret_cast<uint32_t*>(&L);
}

#define LDSM_X4(r0,r1,r2,r3,addr) \
    asm volatile("ldmatrix.sync.aligned.m8n8.x4.shared.b16 {%0,%1,%2,%3}, [%4];" \
        : "=r"(r0), "=r"(r1), "=r"(r2), "=r"(r3) : "r"(addr))

__device__ __forceinline__ void mma_bf16(float* c, const uint32_t* a, uint32_t b0, uint32_t b1){
    asm volatile(
        "mma.sync.aligned.m16n8k16.row.col.f32.bf16.bf16.f32 "
        "{%0,%1,%2,%3}, {%4,%5,%6,%7}, {%8,%9}, {%0,%1,%2,%3};"
        : "+f"(c[0]), "+f"(c[1]), "+f"(c[2]), "+f"(c[3])
        : "r"(a[0]), "r"(a[1]), "r"(a[2]), "r"(a[3]), "r"(b0), "r"(b1));
}

#define CP16(dst, src) asm volatile("cp.async.cg.shared.global [%0], [%1], 16;" :: "r"(dst), "l"(src))
#define CP_COMMIT()    asm volatile("cp.async.commit_group;" ::: "memory")
#define CP_WAIT0()     asm volatile("cp.async.wait_group 0;" ::: "memory")
#define CP_WAIT1()     asm volatile("cp.async.wait_group 1;" ::: "memory")

// smem layout for node GEMMs (bytes)
#define SOF_AH 0
#define SOF_AL 16384
#define SOF_B0 32768            // buf0: H at +0, L at +16384
#define SOF_B1 65536            // buf1
#define SMEM_TG 98304
// edge GEMM
#define EOF_AH 0
#define EOF_AL 32768
#define EOF_BH 65536
#define EOF_BL 73728
#define SMEM_TE 81920

// ---------------- weight preconversion ----------------
__global__ void k_conv_w(const float* __restrict__ Wemb, const float* __restrict__ Wnode,
                         const float* __restrict__ Wedge){
    int t = blockIdx.x * 256 + threadIdx.x;
    if (t < 16384){   // B1: [2][128n][64k]
        int n = t >> 7, kg = t & 127;
        int c = kg >> 6, k = kg & 63;
        float w = Wemb[(n >> 5) * 4096 + kg * 32 + (n & 31)];
        float wh = __bfloat162float(__float2bfloat16_rn(w));
        uint32_t s = (uint32_t)c * 16384 + swoff64(n, k);
        *(__nv_bfloat16*)((char*)g_B1h + s) = __float2bfloat16_rn(wh);
        *(__nv_bfloat16*)((char*)g_B1l + s) = __float2bfloat16_rn(w - wh);
        return;
    }
    t -= 16384;
    if (t < 32768){   // B2: [4][128n][64k]
        int n = t >> 8, kg = t & 255;
        int c = kg >> 6, k = kg & 63;
        float w = Wnode[kg * 128 + n];
        if (kg >= 128) w *= 0.25f;
        float wh = __bfloat162float(__float2bfloat16_rn(w));
        uint32_t s = (uint32_t)c * 16384 + swoff64(n, k);
        *(__nv_bfloat16*)((char*)g_B2h + s) = __float2bfloat16_rn(wh);
        *(__nv_bfloat16*)((char*)g_B2l + s) = __float2bfloat16_rn(w - wh);
        return;
    }
    t -= 32768;
    if (t < 16384){   // edge weights: [4][32n][128k], zero-padded k>=96
        int q = t >> 12, r = t & 4095;
        int n = r >> 7, k = r & 127;
        float w = (k < 96) ? Wedge[q * 3072 + k * 32 + n] : 0.f;
        float wh = __bfloat162float(__float2bfloat16_rn(w));
        uint32_t s = swoff256(n, k);
        *(__nv_bfloat16*)((char*)g_BEh[q] + s) = __float2bfloat16_rn(wh);
        *(__nv_bfloat16*)((char*)g_BEl[q] + s) = __float2bfloat16_rn(w - wh);
    }
}

// ---------------- shared-fragment MMA over one 64-K chunk (warp tile 32x32) ----------------
__device__ __forceinline__ void mma_chunk64(uint32_t Ah, uint32_t Al, uint32_t Bh, uint32_t Bl,
                                            int warp_m, int warp_n, int lane, float acc[2][4][4]){
#pragma unroll
    for (int kc = 0; kc < 4; kc++){
        uint32_t ah[2][4], al[2][4];
#pragma unroll
        for (int tf = 0; tf < 2; tf++){
            int row = warp_m * 32 + tf * 16 + (lane & 15);
            int ch = kc * 2 + (lane >> 4);
            uint32_t off = row * 128 + ((ch ^ (row & 7)) << 4);
            LDSM_X4(ah[tf][0], ah[tf][1], ah[tf][2], ah[tf][3], Ah + off);
            LDSM_X4(al[tf][0], al[tf][1], al[tf][2], al[tf][3], Al + off);
        }
        uint32_t bh[4][2], bl[4][2];
#pragma unroll
        for (int jj = 0; jj < 2; jj++){
            int rowN = warp_n * 32 + jj * 16 + (lane & 7) + ((lane >> 4) << 3);
            int ch = kc * 2 + ((lane >> 3) & 1);
            uint32_t off = rowN * 128 + ((ch ^ (rowN & 7)) << 4);
            uint32_t r0, r1, r2, r3;
            LDSM_X4(r0, r1, r2, r3, Bh + off);
            bh[jj*2][0] = r0;   bh[jj*2][1] = r1;
            bh[jj*2+1][0] = r2; bh[jj*2+1][1] = r3;
            LDSM_X4(r0, r1, r2, r3, Bl + off);
            bl[jj*2][0] = r0;   bl[jj*2][1] = r1;
            bl[jj*2+1][0] = r2; bl[jj*2+1][1] = r3;
        }
#pragma unroll
        for (int tf = 0; tf < 2; tf++)
#pragma unroll
            for (int j = 0; j < 4; j++){
                mma_bf16(acc[tf][j], ah[tf], bh[j][0], bh[j][1]);
                mma_bf16(acc[tf][j], al[tf], bh[j][0], bh[j][1]);
                mma_bf16(acc[tf][j], ah[tf], bl[j][0], bl[j][1]);
            }
    }
}

// convert reg buffer -> swizzled smem (thread owns row m, 16 k starting at k16)
__device__ __forceinline__ void sts_a(char* smem, const float4 v[4], int m, int k16){
    uint4 H0, L0, H1, L1;
    split2(v[0].x, v[0].y, H0.x, L0.x); split2(v[0].z, v[0].w, H0.y, L0.y);
    split2(v[1].x, v[1].y, H0.z, L0.z); split2(v[1].z, v[1].w, H0.w, L0.w);
    split2(v[2].x, v[2].y, H1.x, L1.x); split2(v[2].z, v[2].w, H1.y, L1.y);
    split2(v[3].x, v[3].y, H1.z, L1.z); split2(v[3].z, v[3].w, H1.w, L1.w);
    uint32_t s0 = swoff64(m, k16), s1 = swoff64(m, k16 + 8);
    *(uint4*)(smem + SOF_AH + s0) = H0;
    *(uint4*)(smem + SOF_AH + s1) = H1;
    *(uint4*)(smem + SOF_AL + s0) = L0;
    *(uint4*)(smem + SOF_AL + s1) = L1;
}

__device__ __forceinline__ void cp_b(uint32_t sbuf, const char* srcH, const char* srcL, int tid){
#pragma unroll
    for (int i = 0; i < 2; i++){
        uint32_t o = (uint32_t)(tid + 512 * i) * 16;
        CP16(sbuf + o, srcH + o);
        CP16(sbuf + 16384 + o, srcL + o);
    }
    CP_COMMIT();
}

__device__ __forceinline__ void epilogue32(float* __restrict__ dst, int M0, int warp_m,
                                           int warp_n, int lane, float acc[2][4][4]){
#pragma unroll
    for (int tf = 0; tf < 2; tf++){
        int r0 = M0 + warp_m * 32 + tf * 16 + (lane >> 2);
#pragma unroll
        for (int j = 0; j < 4; j++){
            int col = warp_n * 32 + j * 8 + (lane & 3) * 2;
            if (r0 < NN)
                *(float2*)(dst + (size_t)r0 * 128 + col) =
                    make_float2(fmaxf(acc[tf][j][0], 0.f), fmaxf(acc[tf][j][1], 0.f));
            if (r0 + 8 < NN)
                *(float2*)(dst + (size_t)(r0 + 8) * 128 + col) =
                    make_float2(fmaxf(acc[tf][j][2], 0.f), fmaxf(acc[tf][j][3], 0.f));
        }
    }
}

// A-chunk loaders (thread: row gm, 16 floats at k16)
__device__ __forceinline__ void ldg_a_x(const float* __restrict__ x, int gm, int c, int k16, float4 v[4]){
    v[0] = v[1] = v[2] = v[3] = make_float4(0.f,0.f,0.f,0.f);
    if (gm < NN){
        const float* src = x + (size_t)gm * 128 + c * 64 + k16;
        v[0] = *(const float4*)(src);
        v[1] = *(const float4*)(src + 4);
        v[2] = *(const float4*)(src + 8);
        v[3] = *(const float4*)(src + 12);
    }
}
__device__ __forceinline__ void ldg_a_agg(int gm, int c, int k16, float4 v[4]){
    v[0] = v[1] = v[2] = v[3] = make_float4(0.f,0.f,0.f,0.f);
    if (gm < NN){
        int d = (c - 2) * 2 + (k16 >> 5);
        int u = k16 & 31;
        int r = gm / WW, cc = gm - r * WW;
        int e = -1;
        if (d == 0){ if (r < HH-1) e = gm; }
        else if (d == 1){ if (cc >= 1) e = r*(WW-1) + cc - 1; }
        else if (d == 2){ if (r >= 1) e = gm - WW; }
        else            { if (cc <= WW-2) e = r*(WW-1) + cc; }
        if (e >= 0){
            const float* src = &g_EDGE[d][0] + (size_t)e * 32 + u;
            v[0] = *(const float4*)(src);
            v[1] = *(const float4*)(src + 4);
            v[2] = *(const float4*)(src + 8);
            v[3] = *(const float4*)(src + 12);
        }
    }
}

// ---------------- GEMM1: XQ = relu(x @ Wcat), C=2 chunks ----------------
__global__ __launch_bounds__(512, 1) void k_tg1(const float* __restrict__ x){
    extern __shared__ char smem[];
    const uint32_t sb = smem_u32(smem);
    const int tid = threadIdx.x, wid = tid >> 5, lane = tid & 31;
    const int warp_m = wid >> 2, warp_n = wid & 3;
    const int M0 = blockIdx.x * 128;
    const int m = tid >> 2, k16 = (tid & 3) * 16, gm = M0 + m;

    float acc[2][4][4];
#pragma unroll
    for (int t = 0; t < 2; t++)
#pragma unroll
        for (int j = 0; j < 4; j++)
#pragma unroll
            for (int e = 0; e < 4; e++) acc[t][j][e] = 0.f;

    float4 v[4];
    cp_b(sb + SOF_B0, (const char*)g_B1h, (const char*)g_B1l, tid);
    ldg_a_x(x, gm, 0, k16, v);

#pragma unroll
    for (int c = 0; c < 2; c++){
        sts_a(smem, v, m, k16);
        if (c == 0){
            cp_b(sb + SOF_B1, (const char*)g_B1h + 16384, (const char*)g_B1l + 16384, tid);
            ldg_a_x(x, gm, 1, k16, v);
            CP_WAIT1();
        } else {
            CP_WAIT0();
        }
        __syncthreads();
        uint32_t bbase = sb + ((c & 1) ? SOF_B1 : SOF_B0);
        mma_chunk64(sb + SOF_AH, sb + SOF_AL, bbase, bbase + 16384, warp_m, warp_n, lane, acc);
        __syncthreads();
    }
    epilogue32(g_XQ, M0, warp_m, warp_n, lane, acc);
}

// ---------------- GEMM2: X2 = relu([x | aggs] @ Wnode'), C=4 chunks ----------------
__global__ __launch_bounds__(512, 1) void k_tg2(const float* __restrict__ x){
    extern __shared__ char smem[];
    const uint32_t sb = smem_u32(smem);
    const int tid = threadIdx.x, wid = tid >> 5, lane = tid & 31;
    const int warp_m = wid >> 2, warp_n = wid & 3;
    const int M0 = blockIdx.x * 128;
    const int m = tid >> 2, k16 = (tid & 3) * 16, gm = M0 + m;

    float acc[2][4][4];
#pragma unroll
    for (int t = 0; t < 2; t++)
#pragma unroll
        for (int j = 0; j < 4; j++)
#pragma unroll
            for (int e = 0; e < 4; e++) acc[t][j][e] = 0.f;

    float4 v[4];
    cp_b(sb + SOF_B0, (const char*)g_B2h, (const char*)g_B2l, tid);
    ldg_a_x(x, gm, 0, k16, v);

#pragma unroll
    for (int c = 0; c < 4; c++){
        sts_a(smem, v, m, k16);
        if (c < 3){
            cp_b(sb + (((c + 1) & 1) ? SOF_B1 : SOF_B0),
                 (const char*)g_B2h + (size_t)(c + 1) * 16384,
                 (const char*)g_B2l + (size_t)(c + 1) * 16384, tid);
            if (c + 1 < 2) ldg_a_x(x, gm, c + 1, k16, v);
            else           ldg_a_agg(gm, c + 1, k16, v);
            CP_WAIT1();
        } else {
            CP_WAIT0();
        }
        __syncthreads();
        uint32_t bbase = sb + ((c & 1) ? SOF_B1 : SOF_B0);
        mma_chunk64(sb + SOF_AH, sb + SOF_AL, bbase, bbase + 16384, warp_m, warp_n, lane, acc);
        __syncthreads();
    }
    epilogue32(g_X2, M0, warp_m, warp_n, lane, acc);
}

// =====================================================================
// Edge GEMM via HMMA with shared fragments
// block: 128 edges, 256 threads, 8 warps; warp tile 16m x 32n; K=96 (6 kc)
// =====================================================================
__global__ __launch_bounds__(256, 2) void k_edge(const float* __restrict__ efN,
                                                 const float* __restrict__ efE,
                                                 const float* __restrict__ efS,
                                                 const float* __restrict__ efW,
                                                 int unused){
    extern __shared__ char smem[];
    const uint32_t sb = smem_u32(smem);
    const int q = blockIdx.y;
    const float* ef = (q==0) ? efN : (q==1) ? efE : (q==2) ? efS : efW;
    const int E = (q==0 || q==2) ? E_NS : E_EW;
    const int M0 = blockIdx.x * 128;
    if (M0 >= E) return;
    const int tid = threadIdx.x, wid = tid >> 5, lane = tid & 31;

    // fill A: 128 edges x 96 K (12 k8-chunks)
#pragma unroll
    for (int i = 0; i < 6; i++){
        int lin = tid + 256 * i;
        int m = lin / 12, k8c = lin - m * 12;
        int k8 = k8c * 8;
        int e = M0 + m;
        float4 v0 = make_float4(0.f,0.f,0.f,0.f), v1 = v0;
        if (e < E){
            if (k8c < 4){
                const float* src = ef + (size_t)e * 32 + k8;
                v0 = *(const float4*)(src);
                v1 = *(const float4*)(src + 4);
            } else {
                int s, t;
                if (q == 0){ int r = 1 + e/WW,     c = e%WW;         s = r*WW + c; t = s - WW; }
                else if (q == 1){ int r = e/(WW-1), c = e%(WW-1);    s = r*WW + c; t = s + 1;  }
                else if (q == 2){ int r = e/WW,     c = e%WW;        s = r*WW + c; t = s + WW; }
                else            { int r = e/(WW-1), c = e%(WW-1)+1;  s = r*WW + c; t = s - 1;  }
                int node = (k8c < 8) ? s : t;
                int u = (k8c & 3) * 8;
                const float* src = g_XQ + (size_t)node * 128 + q * 32 + u;
                v0 = *(const float4*)(src);
                v1 = *(const float4*)(src + 4);
            }
        }
        uint4 H, L;
        split2(v0.x, v0.y, H.x, L.x); split2(v0.z, v0.w, H.y, L.y);
        split2(v1.x, v1.y, H.z, L.z); split2(v1.z, v1.w, H.w, L.w);
        uint32_t s = swoff256(m, k8);
        *(uint4*)(smem + EOF_AH + s) = H;
        *(uint4*)(smem + EOF_AL + s) = L;
    }
    {
        const uint4* bh = (const uint4*)g_BEh[q];
        const uint4* bl = (const uint4*)g_BEl[q];
#pragma unroll
        for (int i = 0; i < 2; i++){
            int idx = tid + 256 * i;
            ((uint4*)(smem + EOF_BH))[idx] = bh[idx];
            ((uint4*)(smem + EOF_BL))[idx] = bl[idx];
        }
    }
    __syncthreads();

    float acc[4][4];
#pragma unroll
    for (int j = 0; j < 4; j++)
#pragma unroll
        for (int e = 0; e < 4; e++) acc[j][e] = 0.f;

#pragma unroll
    for (int kc = 0; kc < 6; kc++){
        uint32_t ah[4], al[4];
        {
            int row = wid * 16 + (lane & 15);
            int ch = kc * 2 + (lane >> 4);
            uint32_t off = row * 256 + ((ch ^ (row & 7)) << 4);
            LDSM_X4(ah[0], ah[1], ah[2], ah[3], sb + EOF_AH + off);
            LDSM_X4(al[0], al[1], al[2], al[3], sb + EOF_AL + off);
        }
        uint32_t bh[4][2], bl[4][2];
#pragma unroll
        for (int jj = 0; jj < 2; jj++){
            int rowN = jj * 16 + (lane & 7) + ((lane >> 4) << 3);
            int ch = kc * 2 + ((lane >> 3) & 1);
            uint32_t off = rowN * 256 + ((ch ^ (rowN & 7)) << 4);
            uint32_t r0, r1, r2, r3;
            LDSM_X4(r0, r1, r2, r3, sb + EOF_BH + off);
            bh[jj*2][0] = r0;   bh[jj*2][1] = r1;
            bh[jj*2+1][0] = r2; bh[jj*2+1][1] = r3;
            LDSM_X4(r0, r1, r2, r3, sb + EOF_BL + off);
            bl[jj*2][0] = r0;   bl[jj*2][1] = r1;
            bl[jj*2+1][0] = r2; bl[jj*2+1][1] = r3;
        }
#pragma unroll
        for (int j = 0; j < 4; j++){
            mma_bf16(acc[j], ah, bh[j][0], bh[j][1]);
            mma_bf16(acc[j], al, bh[j][0], bh[j][1]);
            mma_bf16(acc[j], ah, bl[j][0], bl[j][1]);
        }
    }

    float* ED = &g_EDGE[q][0];
    int r0 = M0 + wid * 16 + (lane >> 2);
#pragma unroll
    for (int j = 0; j < 4; j++){
        int col = j * 8 + (lane & 3) * 2;
        if (r0 < E)
            *(float2*)(ED + (size_t)r0 * 32 + col) =
                make_float2(fmaxf(acc[j][0], 0.f), fmaxf(acc[j][1], 0.f));
        if (r0 + 8 < E)
            *(float2*)(ED + (size_t)(r0 + 8) * 32 + col) =
                make_float2(fmaxf(acc[j][2], 0.f), fmaxf(acc[j][3], 0.f));
    }
}

// ---------------- pooling / metadata / edge-feature kernels ----------------
template<typename T>
__global__ void k_pool(T* __restrict__ out){
    int t = blockIdx.x * 256 + threadIdx.x;
    if (t >= NP * 32) return;
    int p = t >> 5, fi = (t & 31) * 4;
    int pr = p / PCC, pc = p % PCC;
    int n00 = (2*pr)*WW + 2*pc;
    const float* base = g_X2 + (size_t)n00*128 + fi;
    float4 a = *(const float4*)(base);
    float4 b = *(const float4*)(base + 128);
    a.x = fmaxf(a.x, b.x); a.y = fmaxf(a.y, b.y);
    a.z = fmaxf(a.z, b.z); a.w = fmaxf(a.w, b.w);
    if (2*pr + 1 < HH){
        float4 c4 = *(const float4*)(base + (size_t)128*WW);
        float4 d4 = *(const float4*)(base + (size_t)128*WW + 128);
        a.x = fmaxf(a.x, fmaxf(c4.x, d4.x));
        a.y = fmaxf(a.y, fmaxf(c4.y, d4.y));
        a.z = fmaxf(a.z, fmaxf(c4.z, d4.z));
        a.w = fmaxf(a.w, fmaxf(c4.w, d4.w));
    }
    T* o = out + (size_t)p*128 + fi;
    o[0] = (T)a.x; o[1] = (T)a.y; o[2] = (T)a.z; o[3] = (T)a.w;
}

template<typename T>
__global__ void k_meta(T* __restrict__ out){
    int t = blockIdx.x * 256 + threadIdx.x;
    if (t < NP){
        out[OFF_POS + 2*t]     = (T)(t / PCC);
        out[OFF_POS + 2*t + 1] = (T)(t % PCC);
        return;
    }
    t -= NP;
    if (t < M_NS){
        int k = 1 + t / PCC, j = t % PCC;
        out[OFF_EIN + 2*t]     = (T)(k*PCC + j);
        out[OFF_EIN + 2*t + 1] = (T)((k-1)*PCC + j);
        return;
    }
    t -= M_NS;
    if (t < M_EW){
        int k = t / 217, j = t % 217;
        int s = k*PCC + j;
        out[OFF_EIE + 2*t]     = (T)s;
        out[OFF_EIE + 2*t + 1] = (T)(s + 1);
        return;
    }
    t -= M_EW;
    if (t < M_NS){
        int k = t / PCC, j = t % PCC;
        int s = k*PCC + j;
        out[OFF_EIS + 2*t]     = (T)s;
        out[OFF_EIS + 2*t + 1] = (T)(s + PCC);
        return;
    }
    t -= M_NS;
    if (t < M_EW){
        int k = t / 217, j = t % 217 + 1;
        int s = k*PCC + j;
        out[OFF_EIW + 2*t]     = (T)s;
        out[OFF_EIW + 2*t + 1] = (T)(s - 1);
        return;
    }
}

template<typename T>
__global__ void k_efeat(T* __restrict__ out){
    const int d = blockIdx.y;
    const int M = (d == 0 || d == 2) ? M_NS : M_EW;
    int t = blockIdx.x * 256 + threadIdx.x;
    if (t >= M * 8) return;
    int m = t >> 3, fi = (t & 7) * 4;
    int e1, stride2 = 1; bool two = true; size_t off;
    if (d == 0){      int k = 1 + m/PCC, j = m%PCC; e1 = (2*k - 1)*WW + 2*j;      off = OFF_FN; }
    else if (d == 1){ int k = m/217,     j = m%217; e1 = 2*k*(WW-1) + 2*j + 1;    stride2 = WW-1; two = (k < 247); off = OFF_FE; }
    else if (d == 2){ int k = m/PCC,     j = m%PCC; e1 = (2*k + 1)*WW + 2*j;      off = OFF_FS; }
    else {            int k = m/217,     j = m%217 + 1; e1 = 2*k*(WW-1) + 2*j - 1; stride2 = WW-1; two = (k < 247); off = OFF_FW; }
    const float* ED = &g_EDGE[d][0];
    float4 a = *(const float4*)(ED + (size_t)e1*32 + fi);
    if (two){
        float4 b = *(const float4*)(ED + (size_t)(e1 + stride2)*32 + fi);
        a.x = fmaxf(a.x, b.x); a.y = fmaxf(a.y, b.y);
        a.z = fmaxf(a.z, b.z); a.w = fmaxf(a.w, b.w);
    }
    T* o = out + off + (size_t)m*32 + fi;
    o[0] = (T)a.x; o[1] = (T)a.y; o[2] = (T)a.z; o[3] = (T)a.w;
}

// =====================================================================
extern "C" void kernel_launch(void* const* d_in, const int* in_sizes, int n_in,
                              void* d_out, int out_size){
    const float* x     = (const float*)d_in[0];
    const float* efN   = (const float*)d_in[6];
    const float* efE   = (const float*)d_in[7];
    const float* efS   = (const float*)d_in[8];
    const float* efW   = (const float*)d_in[9];
    const float* Wemb  = (const float*)d_in[10];
    const float* Wedge = (const float*)d_in[11];
    const float* Wnode = (const float*)d_in[12];

    static bool attr_done = false;
    if (!attr_done){
        cudaFuncSetAttribute(k_tg1, cudaFuncAttributeMaxDynamicSharedMemorySize, SMEM_TG);
        cudaFuncSetAttribute(k_tg2, cudaFuncAttributeMaxDynamicSharedMemorySize, SMEM_TG);
        cudaFuncSetAttribute(k_edge, cudaFuncAttributeMaxDynamicSharedMemorySize, SMEM_TE);
        attr_done = true;
    }

    const int gm = (NN + 127) / 128;             // 1687 tiles
    k_conv_w<<<(65536 + 255)/256, 256>>>(Wemb, Wnode, Wedge);
    k_tg1<<<gm, 512, SMEM_TG>>>(x);
    dim3 ge((E_NS + 127) / 128, 4);
    k_edge<<<ge, 256, SMEM_TE>>>(efN, efE, efS, efW, 0);
    k_tg2<<<gm, 512, SMEM_TG>>>(x);

    const int metaT = NP + 2*M_NS + 2*M_EW;
    dim3 gf((M_NS*8 + 255) / 256, 4);

    if (out_size == OUT_TOTAL){
        float* out = (float*)d_out;
        k_pool<float><<<(NP*32 + 255)/256, 256>>>(out);
        k_meta<float><<<(metaT + 255)/256, 256>>>(out);
        k_efeat<float><<<gf, 256>>>(out);
    } else {
        double* out = (double*)d_out;
        k_pool<double><<<(NP*32 + 255)/256, 256>>>(out);
        k_meta<double><<<(metaT + 255)/256, 256>>>(out);
        k_efeat<double><<<gf, 256>>>(out);
    }
}

// round 8
// speedup vs baseline: 2.8097x; 1.4535x over previous
#include <cuda_runtime.h>
#include <cuda_fp16.h>
#include <cstdint>

// ---------------- static problem constants ----------------
#define HH 495
#define WW 436
#define NN (HH*WW)            // 215820 nodes
#define PRR 248
#define PCC 218
#define NP (PRR*PCC)          // 54064 pooled nodes
#define E_NS ((HH-1)*WW)      // 215384 edges (north & south)
#define E_EW (HH*(WW-1))      // 215325 edges (east & west)
#define M_NS (247*218)
#define M_EW (248*217)

// output layout (float elements)
#define OFF_POS 6920192
#define OFF_EIN 7028320
#define OFF_EIE 7136012
#define OFF_EIS 7243644
#define OFF_EIW 7351336
#define OFF_FN  7458968
#define OFF_FE  9182040
#define OFF_FS  10904152
#define OFF_FW  12627224
#define OUT_TOTAL 14349336

// ---------------- scratch ----------------
__device__ float g_XQ[(size_t)NN*128];
__device__ float g_EDGE[4][(size_t)E_NS*32];
__device__ float g_X2[(size_t)NN*128];
// fp16 weight images in 64-k chunk layout: [chunk][128n][64k], 128B rows, swizzled
__device__ __align__(16) __half g_B1[2][128*64];
__device__ __align__(16) __half g_B2[4][128*64];
// edge weights: 128-k rows (256B), K padded 96->128
__device__ __align__(16) __half g_BE[4][32*128];

// ---------------- helpers ----------------
__device__ __forceinline__ uint32_t smem_u32(const void* p){
    uint32_t a;
    asm("{ .reg .u64 t; cvta.to.shared.u64 t, %1; cvt.u32.u64 %0, t; }" : "=r"(a) : "l"(p));
    return a;
}
// swizzled byte offset, 64-k rows (128B): 8 chunks of 16B XOR row%8
__device__ __forceinline__ uint32_t swoff64(int row, int k){
    return (uint32_t)(row * 128 + (((k >> 3) ^ (row & 7)) << 4) + (k & 7) * 2);
}
// swizzled byte offset, 128-k rows (256B)
__device__ __forceinline__ uint32_t swoff256(int row, int k){
    return (uint32_t)(row * 256 + (((k >> 3) ^ (row & 7)) << 4) + (k & 7) * 2);
}
__device__ __forceinline__ uint32_t pk_h2(float a, float b){
    __half2 h = __floats2half2_rn(a, b);
    return *reinterpret_cast<uint32_t*>(&h);
}

#define LDSM_X4(r0,r1,r2,r3,addr) \
    asm volatile("ldmatrix.sync.aligned.m8n8.x4.shared.b16 {%0,%1,%2,%3}, [%4];" \
        : "=r"(r0), "=r"(r1), "=r"(r2), "=r"(r3) : "r"(addr))

__device__ __forceinline__ void mma_f16(float* c, const uint32_t* a, uint32_t b0, uint32_t b1){
    asm volatile(
        "mma.sync.aligned.m16n8k16.row.col.f32.f16.f16.f32 "
        "{%0,%1,%2,%3}, {%4,%5,%6,%7}, {%8,%9}, {%0,%1,%2,%3};"
        : "+f"(c[0]), "+f"(c[1]), "+f"(c[2]), "+f"(c[3])
        : "r"(a[0]), "r"(a[1]), "r"(a[2]), "r"(a[3]), "r"(b0), "r"(b1));
}

#define CP16(dst, src) asm volatile("cp.async.cg.shared.global [%0], [%1], 16;" :: "r"(dst), "l"(src))
#define CP_COMMIT()    asm volatile("cp.async.commit_group;" ::: "memory")
#define CP_WAIT0()     asm volatile("cp.async.wait_group 0;" ::: "memory")
#define CP_WAIT1()     asm volatile("cp.async.wait_group 1;" ::: "memory")

// smem layout for node GEMMs (bytes)
#define SOF_A  0                // 16KB (128 x 64 fp16)
#define SOF_B0 16384            // 16KB
#define SOF_B1 32768            // 16KB
#define SMEM_TG 49152
// edge GEMM
#define EOF_A 0                 // 32KB (128 x 128 fp16)
#define EOF_B 32768             // 8KB
#define SMEM_TE 40960

// ---------------- weight preconversion ----------------
__global__ void k_conv_w(const float* __restrict__ Wemb, const float* __restrict__ Wnode,
                         const float* __restrict__ Wedge){
    int t = blockIdx.x * 256 + threadIdx.x;
    if (t < 16384){   // B1: [2][128n][64k]
        int n = t >> 7, kg = t & 127;
        int c = kg >> 6, k = kg & 63;
        float w = Wemb[(n >> 5) * 4096 + kg * 32 + (n & 31)];
        *(__half*)((char*)g_B1 + (uint32_t)c * 16384 + swoff64(n, k)) = __float2half_rn(w);
        return;
    }
    t -= 16384;
    if (t < 32768){   // B2: [4][128n][64k]
        int n = t >> 8, kg = t & 255;
        int c = kg >> 6, k = kg & 63;
        float w = Wnode[kg * 128 + n];
        if (kg >= 128) w *= 0.25f;
        *(__half*)((char*)g_B2 + (uint32_t)c * 16384 + swoff64(n, k)) = __float2half_rn(w);
        return;
    }
    t -= 32768;
    if (t < 16384){   // edge weights: [4][32n][128k], zero-padded k>=96
        int q = t >> 12, r = t & 4095;
        int n = r >> 7, k = r & 127;
        float w = (k < 96) ? Wedge[q * 3072 + k * 32 + n] : 0.f;
        *(__half*)((char*)g_BE[q] + swoff256(n, k)) = __float2half_rn(w);
    }
}

// ---------------- single-pass fp16 MMA over one 64-K chunk (warp tile 32x32) ----------------
__device__ __forceinline__ void mma_chunk64(uint32_t Ab, uint32_t Bb,
                                            int warp_m, int warp_n, int lane, float acc[2][4][4]){
#pragma unroll
    for (int kc = 0; kc < 4; kc++){
        uint32_t a[2][4];
#pragma unroll
        for (int tf = 0; tf < 2; tf++){
            int row = warp_m * 32 + tf * 16 + (lane & 15);
            int ch = kc * 2 + (lane >> 4);
            uint32_t off = row * 128 + ((ch ^ (row & 7)) << 4);
            LDSM_X4(a[tf][0], a[tf][1], a[tf][2], a[tf][3], Ab + off);
        }
        uint32_t bfr[4][2];
#pragma unroll
        for (int jj = 0; jj < 2; jj++){
            int rowN = warp_n * 32 + jj * 16 + (lane & 7) + ((lane >> 4) << 3);
            int ch = kc * 2 + ((lane >> 3) & 1);
            uint32_t off = rowN * 128 + ((ch ^ (rowN & 7)) << 4);
            uint32_t r0, r1, r2, r3;
            LDSM_X4(r0, r1, r2, r3, Bb + off);
            bfr[jj*2][0] = r0;   bfr[jj*2][1] = r1;
            bfr[jj*2+1][0] = r2; bfr[jj*2+1][1] = r3;
        }
#pragma unroll
        for (int tf = 0; tf < 2; tf++)
#pragma unroll
            for (int j = 0; j < 4; j++)
                mma_f16(acc[tf][j], a[tf], bfr[j][0], bfr[j][1]);
    }
}

// reg buffer -> fp16 swizzled smem (thread owns row m, 16 k starting at k16)
__device__ __forceinline__ void sts_a(char* smem, const float4 v[4], int m, int k16){
    uint4 H0, H1;
    H0.x = pk_h2(v[0].x, v[0].y); H0.y = pk_h2(v[0].z, v[0].w);
    H0.z = pk_h2(v[1].x, v[1].y); H0.w = pk_h2(v[1].z, v[1].w);
    H1.x = pk_h2(v[2].x, v[2].y); H1.y = pk_h2(v[2].z, v[2].w);
    H1.z = pk_h2(v[3].x, v[3].y); H1.w = pk_h2(v[3].z, v[3].w);
    *(uint4*)(smem + SOF_A + swoff64(m, k16))     = H0;
    *(uint4*)(smem + SOF_A + swoff64(m, k16 + 8)) = H1;
}

__device__ __forceinline__ void cp_b(uint32_t sbuf, const char* src, int tid){
#pragma unroll
    for (int i = 0; i < 2; i++){
        uint32_t o = (uint32_t)(tid + 512 * i) * 16;
        CP16(sbuf + o, src + o);
    }
    CP_COMMIT();
}

__device__ __forceinline__ void epilogue32(float* __restrict__ dst, int M0, int warp_m,
                                           int warp_n, int lane, float acc[2][4][4]){
#pragma unroll
    for (int tf = 0; tf < 2; tf++){
        int r0 = M0 + warp_m * 32 + tf * 16 + (lane >> 2);
#pragma unroll
        for (int j = 0; j < 4; j++){
            int col = warp_n * 32 + j * 8 + (lane & 3) * 2;
            if (r0 < NN)
                *(float2*)(dst + (size_t)r0 * 128 + col) =
                    make_float2(fmaxf(acc[tf][j][0], 0.f), fmaxf(acc[tf][j][1], 0.f));
            if (r0 + 8 < NN)
                *(float2*)(dst + (size_t)(r0 + 8) * 128 + col) =
                    make_float2(fmaxf(acc[tf][j][2], 0.f), fmaxf(acc[tf][j][3], 0.f));
        }
    }
}

// A-chunk loaders (thread: row gm, 16 floats at k16)
__device__ __forceinline__ void ldg_a_x(const float* __restrict__ x, int gm, int c, int k16, float4 v[4]){
    v[0] = v[1] = v[2] = v[3] = make_float4(0.f,0.f,0.f,0.f);
    if (gm < NN){
        const float* src = x + (size_t)gm * 128 + c * 64 + k16;
        v[0] = *(const float4*)(src);
        v[1] = *(const float4*)(src + 4);
        v[2] = *(const float4*)(src + 8);
        v[3] = *(const float4*)(src + 12);
    }
}
__device__ __forceinline__ void ldg_a_agg(int gm, int c, int k16, float4 v[4]){
    v[0] = v[1] = v[2] = v[3] = make_float4(0.f,0.f,0.f,0.f);
    if (gm < NN){
        int d = (c - 2) * 2 + (k16 >> 5);
        int u = k16 & 31;
        int r = gm / WW, cc = gm - r * WW;
        int e = -1;
        if (d == 0){ if (r < HH-1) e = gm; }
        else if (d == 1){ if (cc >= 1) e = r*(WW-1) + cc - 1; }
        else if (d == 2){ if (r >= 1) e = gm - WW; }
        else            { if (cc <= WW-2) e = r*(WW-1) + cc; }
        if (e >= 0){
            const float* src = &g_EDGE[d][0] + (size_t)e * 32 + u;
            v[0] = *(const float4*)(src);
            v[1] = *(const float4*)(src + 4);
            v[2] = *(const float4*)(src + 8);
            v[3] = *(const float4*)(src + 12);
        }
    }
}

// ---------------- GEMM1: XQ = relu(x @ Wcat), C=2 chunks ----------------
__global__ __launch_bounds__(512, 1) void k_tg1(const float* __restrict__ x){
    extern __shared__ char smem[];
    const uint32_t sb = smem_u32(smem);
    const int tid = threadIdx.x, wid = tid >> 5, lane = tid & 31;
    const int warp_m = wid >> 2, warp_n = wid & 3;
    const int M0 = blockIdx.x * 128;
    const int m = tid >> 2, k16 = (tid & 3) * 16, gm = M0 + m;

    float acc[2][4][4];
#pragma unroll
    for (int t = 0; t < 2; t++)
#pragma unroll
        for (int j = 0; j < 4; j++)
#pragma unroll
            for (int e = 0; e < 4; e++) acc[t][j][e] = 0.f;

    float4 v[4];
    cp_b(sb + SOF_B0, (const char*)g_B1, tid);
    ldg_a_x(x, gm, 0, k16, v);

#pragma unroll
    for (int c = 0; c < 2; c++){
        sts_a(smem, v, m, k16);
        if (c == 0){
            cp_b(sb + SOF_B1, (const char*)g_B1 + 16384, tid);
            ldg_a_x(x, gm, 1, k16, v);
            CP_WAIT1();
        } else {
            CP_WAIT0();
        }
        __syncthreads();
        uint32_t bbase = sb + ((c & 1) ? SOF_B1 : SOF_B0);
        mma_chunk64(sb + SOF_A, bbase, warp_m, warp_n, lane, acc);
        __syncthreads();
    }
    epilogue32(g_XQ, M0, warp_m, warp_n, lane, acc);
}

// ---------------- GEMM2: X2 = relu([x | aggs] @ Wnode'), C=4 chunks ----------------
__global__ __launch_bounds__(512, 1) void k_tg2(const float* __restrict__ x){
    extern __shared__ char smem[];
    const uint32_t sb = smem_u32(smem);
    const int tid = threadIdx.x, wid = tid >> 5, lane = tid & 31;
    const int warp_m = wid >> 2, warp_n = wid & 3;
    const int M0 = blockIdx.x * 128;
    const int m = tid >> 2, k16 = (tid & 3) * 16, gm = M0 + m;

    float acc[2][4][4];
#pragma unroll
    for (int t = 0; t < 2; t++)
#pragma unroll
        for (int j = 0; j < 4; j++)
#pragma unroll
            for (int e = 0; e < 4; e++) acc[t][j][e] = 0.f;

    float4 v[4];
    cp_b(sb + SOF_B0, (const char*)g_B2, tid);
    ldg_a_x(x, gm, 0, k16, v);

#pragma unroll
    for (int c = 0; c < 4; c++){
        sts_a(smem, v, m, k16);
        if (c < 3){
            cp_b(sb + (((c + 1) & 1) ? SOF_B1 : SOF_B0),
                 (const char*)g_B2 + (size_t)(c + 1) * 16384, tid);
            if (c + 1 < 2) ldg_a_x(x, gm, c + 1, k16, v);
            else           ldg_a_agg(gm, c + 1, k16, v);
            CP_WAIT1();
        } else {
            CP_WAIT0();
        }
        __syncthreads();
        uint32_t bbase = sb + ((c & 1) ? SOF_B1 : SOF_B0);
        mma_chunk64(sb + SOF_A, bbase, warp_m, warp_n, lane, acc);
        __syncthreads();
    }
    epilogue32(g_X2, M0, warp_m, warp_n, lane, acc);
}

// =====================================================================
// Edge GEMM via fp16 HMMA
// block: 128 edges, 256 threads, 8 warps; warp tile 16m x 32n; K=96 (6 kc)
// =====================================================================
__global__ __launch_bounds__(256, 2) void k_edge(const float* __restrict__ efN,
                                                 const float* __restrict__ efE,
                                                 const float* __restrict__ efS,
                                                 const float* __restrict__ efW,
                                                 int unused){
    extern __shared__ char smem[];
    const uint32_t sb = smem_u32(smem);
    const int q = blockIdx.y;
    const float* ef = (q==0) ? efN : (q==1) ? efE : (q==2) ? efS : efW;
    const int E = (q==0 || q==2) ? E_NS : E_EW;
    const int M0 = blockIdx.x * 128;
    if (M0 >= E) return;
    const int tid = threadIdx.x, wid = tid >> 5, lane = tid & 31;

    // fill A: 128 edges x 96 K (12 k8-chunks)
#pragma unroll
    for (int i = 0; i < 6; i++){
        int lin = tid + 256 * i;
        int m = lin / 12, k8c = lin - m * 12;
        int k8 = k8c * 8;
        int e = M0 + m;
        float4 v0 = make_float4(0.f,0.f,0.f,0.f), v1 = v0;
        if (e < E){
            if (k8c < 4){
                const float* src = ef + (size_t)e * 32 + k8;
                v0 = *(const float4*)(src);
                v1 = *(const float4*)(src + 4);
            } else {
                int s, t;
                if (q == 0){ int r = 1 + e/WW,     c = e%WW;         s = r*WW + c; t = s - WW; }
                else if (q == 1){ int r = e/(WW-1), c = e%(WW-1);    s = r*WW + c; t = s + 1;  }
                else if (q == 2){ int r = e/WW,     c = e%WW;        s = r*WW + c; t = s + WW; }
                else            { int r = e/(WW-1), c = e%(WW-1)+1;  s = r*WW + c; t = s - 1;  }
                int node = (k8c < 8) ? s : t;
                int u = (k8c & 3) * 8;
                const float* src = g_XQ + (size_t)node * 128 + q * 32 + u;
                v0 = *(const float4*)(src);
                v1 = *(const float4*)(src + 4);
            }
        }
        uint4 H;
        H.x = pk_h2(v0.x, v0.y); H.y = pk_h2(v0.z, v0.w);
        H.z = pk_h2(v1.x, v1.y); H.w = pk_h2(v1.z, v1.w);
        *(uint4*)(smem + EOF_A + swoff256(m, k8)) = H;
    }
    {
        const uint4* bh = (const uint4*)g_BE[q];
#pragma unroll
        for (int i = 0; i < 2; i++){
            int idx = tid + 256 * i;
            ((uint4*)(smem + EOF_B))[idx] = bh[idx];
        }
    }
    __syncthreads();

    float acc[4][4];
#pragma unroll
    for (int j = 0; j < 4; j++)
#pragma unroll
        for (int e = 0; e < 4; e++) acc[j][e] = 0.f;

#pragma unroll
    for (int kc = 0; kc < 6; kc++){
        uint32_t a[4];
        {
            int row = wid * 16 + (lane & 15);
            int ch = kc * 2 + (lane >> 4);
            uint32_t off = row * 256 + ((ch ^ (row & 7)) << 4);
            LDSM_X4(a[0], a[1], a[2], a[3], sb + EOF_A + off);
        }
        uint32_t bfr[4][2];
#pragma unroll
        for (int jj = 0; jj < 2; jj++){
            int rowN = jj * 16 + (lane & 7) + ((lane >> 4) << 3);
            int ch = kc * 2 + ((lane >> 3) & 1);
            uint32_t off = rowN * 256 + ((ch ^ (rowN & 7)) << 4);
            uint32_t r0, r1, r2, r3;
            LDSM_X4(r0, r1, r2, r3, sb + EOF_B + off);
            bfr[jj*2][0] = r0;   bfr[jj*2][1] = r1;
            bfr[jj*2+1][0] = r2; bfr[jj*2+1][1] = r3;
        }
#pragma unroll
        for (int j = 0; j < 4; j++)
            mma_f16(acc[j], a, bfr[j][0], bfr[j][1]);
    }

    float* ED = &g_EDGE[q][0];
    int r0 = M0 + wid * 16 + (lane >> 2);
#pragma unroll
    for (int j = 0; j < 4; j++){
        int col = j * 8 + (lane & 3) * 2;
        if (r0 < E)
            *(float2*)(ED + (size_t)r0 * 32 + col) =
                make_float2(fmaxf(acc[j][0], 0.f), fmaxf(acc[j][1], 0.f));
        if (r0 + 8 < E)
            *(float2*)(ED + (size_t)(r0 + 8) * 32 + col) =
                make_float2(fmaxf(acc[j][2], 0.f), fmaxf(acc[j][3], 0.f));
    }
}

// ---------------- pooling / metadata / edge-feature kernels ----------------
template<typename T>
__global__ void k_pool(T* __restrict__ out){
    int t = blockIdx.x * 256 + threadIdx.x;
    if (t >= NP * 32) return;
    int p = t >> 5, fi = (t & 31) * 4;
    int pr = p / PCC, pc = p % PCC;
    int n00 = (2*pr)*WW + 2*pc;
    const float* base = g_X2 + (size_t)n00*128 + fi;
    float4 a = *(const float4*)(base);
    float4 b = *(const float4*)(base + 128);
    a.x = fmaxf(a.x, b.x); a.y = fmaxf(a.y, b.y);
    a.z = fmaxf(a.z, b.z); a.w = fmaxf(a.w, b.w);
    if (2*pr + 1 < HH){
        float4 c4 = *(const float4*)(base + (size_t)128*WW);
        float4 d4 = *(const float4*)(base + (size_t)128*WW + 128);
        a.x = fmaxf(a.x, fmaxf(c4.x, d4.x));
        a.y = fmaxf(a.y, fmaxf(c4.y, d4.y));
        a.z = fmaxf(a.z, fmaxf(c4.z, d4.z));
        a.w = fmaxf(a.w, fmaxf(c4.w, d4.w));
    }
    T* o = out + (size_t)p*128 + fi;
    o[0] = (T)a.x; o[1] = (T)a.y; o[2] = (T)a.z; o[3] = (T)a.w;
}

template<typename T>
__global__ void k_meta(T* __restrict__ out){
    int t = blockIdx.x * 256 + threadIdx.x;
    if (t < NP){
        out[OFF_POS + 2*t]     = (T)(t / PCC);
        out[OFF_POS + 2*t + 1] = (T)(t % PCC);
        return;
    }
    t -= NP;
    if (t < M_NS){
        int k = 1 + t / PCC, j = t % PCC;
        out[OFF_EIN + 2*t]     = (T)(k*PCC + j);
        out[OFF_EIN + 2*t + 1] = (T)((k-1)*PCC + j);
        return;
    }
    t -= M_NS;
    if (t < M_EW){
        int k = t / 217, j = t % 217;
        int s = k*PCC + j;
        out[OFF_EIE + 2*t]     = (T)s;
        out[OFF_EIE + 2*t + 1] = (T)(s + 1);
        return;
    }
    t -= M_EW;
    if (t < M_NS){
        int k = t / PCC, j = t % PCC;
        int s = k*PCC + j;
        out[OFF_EIS + 2*t]     = (T)s;
        out[OFF_EIS + 2*t + 1] = (T)(s + PCC);
        return;
    }
    t -= M_NS;
    if (t < M_EW){
        int k = t / 217, j = t % 217 + 1;
        int s = k*PCC + j;
        out[OFF_EIW + 2*t]     = (T)s;
        out[OFF_EIW + 2*t + 1] = (T)(s - 1);
        return;
    }
}

template<typename T>
__global__ void k_efeat(T* __restrict__ out){
    const int d = blockIdx.y;
    const int M = (d == 0 || d == 2) ? M_NS : M_EW;
    int t = blockIdx.x * 256 + threadIdx.x;
    if (t >= M * 8) return;
    int m = t >> 3, fi = (t & 7) * 4;
    int e1, stride2 = 1; bool two = true; size_t off;
    if (d == 0){      int k = 1 + m/PCC, j = m%PCC; e1 = (2*k - 1)*WW + 2*j;      off = OFF_FN; }
    else if (d == 1){ int k = m/217,     j = m%217; e1 = 2*k*(WW-1) + 2*j + 1;    stride2 = WW-1; two = (k < 247); off = OFF_FE; }
    else if (d == 2){ int k = m/PCC,     j = m%PCC; e1 = (2*k + 1)*WW + 2*j;      off = OFF_FS; }
    else {            int k = m/217,     j = m%217 + 1; e1 = 2*k*(WW-1) + 2*j - 1; stride2 = WW-1; two = (k < 247); off = OFF_FW; }
    const float* ED = &g_EDGE[d][0];
    float4 a = *(const float4*)(ED + (size_t)e1*32 + fi);
    if (two){
        float4 b = *(const float4*)(ED + (size_t)(e1 + stride2)*32 + fi);
        a.x = fmaxf(a.x, b.x); a.y = fmaxf(a.y, b.y);
        a.z = fmaxf(a.z, b.z); a.w = fmaxf(a.w, b.w);
    }
    T* o = out + off + (size_t)m*32 + fi;
    o[0] = (T)a.x; o[1] = (T)a.y; o[2] = (T)a.z; o[3] = (T)a.w;
}

// =====================================================================
extern "C" void kernel_launch(void* const* d_in, const int* in_sizes, int n_in,
                              void* d_out, int out_size){
    const float* x     = (const float*)d_in[0];
    const float* efN   = (const float*)d_in[6];
    const float* efE   = (const float*)d_in[7];
    const float* efS   = (const float*)d_in[8];
    const float* efW   = (const float*)d_in[9];
    const float* Wemb  = (const float*)d_in[10];
    const float* Wedge = (const float*)d_in[11];
    const float* Wnode = (const float*)d_in[12];

    static bool attr_done = false;
    if (!attr_done){
        cudaFuncSetAttribute(k_tg1, cudaFuncAttributeMaxDynamicSharedMemorySize, SMEM_TG);
        cudaFuncSetAttribute(k_tg2, cudaFuncAttributeMaxDynamicSharedMemorySize, SMEM_TG);
        cudaFuncSetAttribute(k_edge, cudaFuncAttributeMaxDynamicSharedMemorySize, SMEM_TE);
        attr_done = true;
    }

    const int gm = (NN + 127) / 128;             // 1687 tiles
    k_conv_w<<<(65536 + 255)/256, 256>>>(Wemb, Wnode, Wedge);
    k_tg1<<<gm, 512, SMEM_TG>>>(x);
    dim3 ge((E_NS + 127) / 128, 4);
    k_edge<<<ge, 256, SMEM_TE>>>(efN, efE, efS, efW, 0);
    k_tg2<<<gm, 512, SMEM_TG>>>(x);

    const int metaT = NP + 2*M_NS + 2*M_EW;
    dim3 gf((M_NS*8 + 255) / 256, 4);

    if (out_size == OUT_TOTAL){
        float* out = (float*)d_out;
        k_pool<float><<<(NP*32 + 255)/256, 256>>>(out);
        k_meta<float><<<(metaT + 255)/256, 256>>>(out);
        k_efeat<float><<<gf, 256>>>(out);
    } else {
        double* out = (double*)d_out;
        k_pool<double><<<(NP*32 + 255)/256, 256>>>(out);
        k_meta<double><<<(metaT + 255)/256, 256>>>(out);
        k_efeat<double><<<gf, 256>>>(out);
    }
}

// round 9
// speedup vs baseline: 3.0824x; 1.0970x over previous
#include <cuda_runtime.h>
#include <cuda_fp16.h>
#include <cstdint>

// ---------------- static problem constants ----------------
#define HH 495
#define WW 436
#define NN (HH*WW)            // 215820 nodes
#define PRR 248
#define PCC 218
#define NP (PRR*PCC)          // 54064 pooled nodes
#define E_NS ((HH-1)*WW)      // 215384 edges (north & south)
#define E_EW (HH*(WW-1))      // 215325 edges (east & west)
#define M_NS (247*218)
#define M_EW (248*217)

// output layout (float elements)
#define OFF_POS 6920192
#define OFF_EIN 7028320
#define OFF_EIE 7136012
#define OFF_EIS 7243644
#define OFF_EIW 7351336
#define OFF_FN  7458968
#define OFF_FE  9182040
#define OFF_FS  10904152
#define OFF_FW  12627224
#define OUT_TOTAL 14349336

// ---------------- scratch ----------------
__device__ __align__(16) __half g_XQ[(size_t)NN*128];   // fp16 (free: edge GEMM re-converts anyway)
__device__ float g_EDGE[4][(size_t)E_NS*32];
// fp16 weight images, [chunk][128n][64k], 128B rows, swizzled
__device__ __align__(16) __half g_B1[2][128*64];
__device__ __align__(16) __half g_B2[4][128*64];
// edge weights: 128-k rows (256B), K padded 96->128
__device__ __align__(16) __half g_BE[4][32*128];

// ---------------- helpers ----------------
__device__ __forceinline__ uint32_t smem_u32(const void* p){
    uint32_t a;
    asm("{ .reg .u64 t; cvta.to.shared.u64 t, %1; cvt.u32.u64 %0, t; }" : "=r"(a) : "l"(p));
    return a;
}
__device__ __forceinline__ uint32_t swoff64(int row, int k){
    return (uint32_t)(row * 128 + (((k >> 3) ^ (row & 7)) << 4) + (k & 7) * 2);
}
__device__ __forceinline__ uint32_t swoff256(int row, int k){
    return (uint32_t)(row * 256 + (((k >> 3) ^ (row & 7)) << 4) + (k & 7) * 2);
}
__device__ __forceinline__ uint32_t pk_h2(float a, float b){
    __half2 h = __floats2half2_rn(a, b);
    return *reinterpret_cast<uint32_t*>(&h);
}

#define LDSM_X4(r0,r1,r2,r3,addr) \
    asm volatile("ldmatrix.sync.aligned.m8n8.x4.shared.b16 {%0,%1,%2,%3}, [%4];" \
        : "=r"(r0), "=r"(r1), "=r"(r2), "=r"(r3) : "r"(addr))

__device__ __forceinline__ void mma_f16(float* c, const uint32_t* a, uint32_t b0, uint32_t b1){
    asm volatile(
        "mma.sync.aligned.m16n8k16.row.col.f32.f16.f16.f32 "
        "{%0,%1,%2,%3}, {%4,%5,%6,%7}, {%8,%9}, {%0,%1,%2,%3};"
        : "+f"(c[0]), "+f"(c[1]), "+f"(c[2]), "+f"(c[3])
        : "r"(a[0]), "r"(a[1]), "r"(a[2]), "r"(a[3]), "r"(b0), "r"(b1));
}

#define CP16(dst, src) asm volatile("cp.async.cg.shared.global [%0], [%1], 16;" :: "r"(dst), "l"(src))
#define CP_COMMIT()    asm volatile("cp.async.commit_group;" ::: "memory")
#define CP_WAIT0()     asm volatile("cp.async.wait_group 0;" ::: "memory")
#define CP_WAIT1()     asm volatile("cp.async.wait_group 1;" ::: "memory")

// smem layout for node GEMMs (bytes): A double buffer + B triple ring
#define SOF_A0 0
#define SOF_A1 16384
#define SOF_B  32768            // + 16384*i, i=0..2
#define SMEM_TG 81920
// edge GEMM
#define EOF_A 0                 // 32KB (128 x 128 fp16)
#define EOF_B 32768             // 8KB
#define SMEM_TE 40960

// ---------------- weight preconversion ----------------
__global__ void k_conv_w(const float* __restrict__ Wemb, const float* __restrict__ Wnode,
                         const float* __restrict__ Wedge){
    int t = blockIdx.x * 256 + threadIdx.x;
    if (t < 16384){   // B1: [2][128n][64k]
        int n = t >> 7, kg = t & 127;
        int c = kg >> 6, k = kg & 63;
        float w = Wemb[(n >> 5) * 4096 + kg * 32 + (n & 31)];
        *(__half*)((char*)g_B1 + (uint32_t)c * 16384 + swoff64(n, k)) = __float2half_rn(w);
        return;
    }
    t -= 16384;
    if (t < 32768){   // B2: [4][128n][64k]
        int n = t >> 8, kg = t & 255;
        int c = kg >> 6, k = kg & 63;
        float w = Wnode[kg * 128 + n];
        if (kg >= 128) w *= 0.25f;
        *(__half*)((char*)g_B2 + (uint32_t)c * 16384 + swoff64(n, k)) = __float2half_rn(w);
        return;
    }
    t -= 32768;
    if (t < 16384){   // edge weights: [4][32n][128k], zero-padded k>=96
        int q = t >> 12, r = t & 4095;
        int n = r >> 7, k = r & 127;
        float w = (k < 96) ? Wedge[q * 3072 + k * 32 + n] : 0.f;
        *(__half*)((char*)g_BE[q] + swoff256(n, k)) = __float2half_rn(w);
    }
}

// zero the pooled-output region (atomicMax target)
__global__ void k_init(float* __restrict__ out){
    int t = blockIdx.x * 256 + threadIdx.x;
    if (t < NP * 32) ((float4*)out)[t] = make_float4(0.f, 0.f, 0.f, 0.f);
}

// ---------------- single-pass fp16 MMA over one 64-K chunk (warp tile 32x32) ----------------
__device__ __forceinline__ void mma_chunk64(uint32_t Ab, uint32_t Bb,
                                            int warp_m, int warp_n, int lane, float acc[2][4][4]){
#pragma unroll
    for (int kc = 0; kc < 4; kc++){
        uint32_t a[2][4];
#pragma unroll
        for (int tf = 0; tf < 2; tf++){
            int row = warp_m * 32 + tf * 16 + (lane & 15);
            int ch = kc * 2 + (lane >> 4);
            uint32_t off = row * 128 + ((ch ^ (row & 7)) << 4);
            LDSM_X4(a[tf][0], a[tf][1], a[tf][2], a[tf][3], Ab + off);
        }
        uint32_t bfr[4][2];
#pragma unroll
        for (int jj = 0; jj < 2; jj++){
            int rowN = warp_n * 32 + jj * 16 + (lane & 7) + ((lane >> 4) << 3);
            int ch = kc * 2 + ((lane >> 3) & 1);
            uint32_t off = rowN * 128 + ((ch ^ (rowN & 7)) << 4);
            uint32_t r0, r1, r2, r3;
            LDSM_X4(r0, r1, r2, r3, Bb + off);
            bfr[jj*2][0] = r0;   bfr[jj*2][1] = r1;
            bfr[jj*2+1][0] = r2; bfr[jj*2+1][1] = r3;
        }
#pragma unroll
        for (int tf = 0; tf < 2; tf++)
#pragma unroll
            for (int j = 0; j < 4; j++)
                mma_f16(acc[tf][j], a[tf], bfr[j][0], bfr[j][1]);
    }
}

// reg buffer -> fp16 swizzled smem A buffer
__device__ __forceinline__ void sts_a(char* smem, uint32_t abase, const float4 v[4], int m, int k16){
    uint4 H0, H1;
    H0.x = pk_h2(v[0].x, v[0].y); H0.y = pk_h2(v[0].z, v[0].w);
    H0.z = pk_h2(v[1].x, v[1].y); H0.w = pk_h2(v[1].z, v[1].w);
    H1.x = pk_h2(v[2].x, v[2].y); H1.y = pk_h2(v[2].z, v[2].w);
    H1.z = pk_h2(v[3].x, v[3].y); H1.w = pk_h2(v[3].z, v[3].w);
    *(uint4*)(smem + abase + swoff64(m, k16))     = H0;
    *(uint4*)(smem + abase + swoff64(m, k16 + 8)) = H1;
}

__device__ __forceinline__ void cp_b(uint32_t sbuf, const char* src, int tid){
#pragma unroll
    for (int i = 0; i < 2; i++){
        uint32_t o = (uint32_t)(tid + 512 * i) * 16;
        CP16(sbuf + o, src + o);
    }
    CP_COMMIT();
}

// A-chunk loaders (thread: row gm, 16 floats at k16)
__device__ __forceinline__ void ldg_a_x(const float* __restrict__ x, int gm, int c, int k16, float4 v[4]){
    v[0] = v[1] = v[2] = v[3] = make_float4(0.f,0.f,0.f,0.f);
    if (gm < NN){
        const float* src = x + (size_t)gm * 128 + c * 64 + k16;
        v[0] = *(const float4*)(src);
        v[1] = *(const float4*)(src + 4);
        v[2] = *(const float4*)(src + 8);
        v[3] = *(const float4*)(src + 12);
    }
}
__device__ __forceinline__ void ldg_a_agg(int gm, int c, int k16, float4 v[4]){
    v[0] = v[1] = v[2] = v[3] = make_float4(0.f,0.f,0.f,0.f);
    if (gm < NN){
        int d = (c - 2) * 2 + (k16 >> 5);
        int u = k16 & 31;
        int r = gm / WW, cc = gm - r * WW;
        int e = -1;
        if (d == 0){ if (r < HH-1) e = gm; }
        else if (d == 1){ if (cc >= 1) e = r*(WW-1) + cc - 1; }
        else if (d == 2){ if (r >= 1) e = gm - WW; }
        else            { if (cc <= WW-2) e = r*(WW-1) + cc; }
        if (e >= 0){
            const float* src = &g_EDGE[d][0] + (size_t)e * 32 + u;
            v[0] = *(const float4*)(src);
            v[1] = *(const float4*)(src + 4);
            v[2] = *(const float4*)(src + 8);
            v[3] = *(const float4*)(src + 12);
        }
    }
}

// ---------------- GEMM1: XQ(fp16) = relu(x @ Wcat), C=2 chunks ----------------
__global__ __launch_bounds__(512, 1) void k_tg1(const float* __restrict__ x){
    extern __shared__ char smem[];
    const uint32_t sb = smem_u32(smem);
    const int tid = threadIdx.x, wid = tid >> 5, lane = tid & 31;
    const int warp_m = wid >> 2, warp_n = wid & 3;
    const int M0 = blockIdx.x * 128;
    const int m = tid >> 2, k16 = (tid & 3) * 16, gm = M0 + m;

    float acc[2][4][4];
#pragma unroll
    for (int t = 0; t < 2; t++)
#pragma unroll
        for (int j = 0; j < 4; j++)
#pragma unroll
            for (int e = 0; e < 4; e++) acc[t][j][e] = 0.f;

    float4 v[4];
    cp_b(sb + SOF_B, (const char*)g_B1, tid);
    ldg_a_x(x, gm, 0, k16, v);

#pragma unroll
    for (int c = 0; c < 2; c++){
        uint32_t abase = (c & 1) ? SOF_A1 : SOF_A0;
        sts_a(smem, abase, v, m, k16);
        if (c == 0){
            cp_b(sb + SOF_B + 16384, (const char*)g_B1 + 16384, tid);
            ldg_a_x(x, gm, 1, k16, v);
            CP_WAIT1();
        } else {
            CP_WAIT0();
        }
        __syncthreads();
        mma_chunk64(sb + abase, sb + SOF_B + (c % 3) * 16384, warp_m, warp_n, lane, acc);
    }
    // epilogue: fp16 store
#pragma unroll
    for (int tf = 0; tf < 2; tf++){
        int r0 = M0 + warp_m * 32 + tf * 16 + (lane >> 2);
#pragma unroll
        for (int j = 0; j < 4; j++){
            int col = warp_n * 32 + j * 8 + (lane & 3) * 2;
            if (r0 < NN)
                *(uint32_t*)(g_XQ + (size_t)r0 * 128 + col) =
                    pk_h2(fmaxf(acc[tf][j][0], 0.f), fmaxf(acc[tf][j][1], 0.f));
            if (r0 + 8 < NN)
                *(uint32_t*)(g_XQ + (size_t)(r0 + 8) * 128 + col) =
                    pk_h2(fmaxf(acc[tf][j][2], 0.f), fmaxf(acc[tf][j][3], 0.f));
        }
    }
}

// ---------------- GEMM2 + fused 2x2 pooling, C=4 chunks ----------------
__global__ __launch_bounds__(512, 1) void k_tg2(const float* __restrict__ x,
                                                float* __restrict__ out){
    extern __shared__ char smem[];
    const uint32_t sb = smem_u32(smem);
    const int tid = threadIdx.x, wid = tid >> 5, lane = tid & 31;
    const int warp_m = wid >> 2, warp_n = wid & 3;
    const int M0 = blockIdx.x * 128;
    const int m = tid >> 2, k16 = (tid & 3) * 16, gm = M0 + m;

    float acc[2][4][4];
#pragma unroll
    for (int t = 0; t < 2; t++)
#pragma unroll
        for (int j = 0; j < 4; j++)
#pragma unroll
            for (int e = 0; e < 4; e++) acc[t][j][e] = 0.f;

    float4 v[4];
    cp_b(sb + SOF_B, (const char*)g_B2, tid);
    ldg_a_x(x, gm, 0, k16, v);

#pragma unroll
    for (int c = 0; c < 4; c++){
        uint32_t abase = (c & 1) ? SOF_A1 : SOF_A0;
        sts_a(smem, abase, v, m, k16);
        if (c < 3){
            cp_b(sb + SOF_B + ((c + 1) % 3) * 16384,
                 (const char*)g_B2 + (size_t)(c + 1) * 16384, tid);
            if (c + 1 < 2) ldg_a_x(x, gm, c + 1, k16, v);
            else           ldg_a_agg(gm, c + 1, k16, v);
            CP_WAIT1();
        } else {
            CP_WAIT0();
        }
        __syncthreads();
        mma_chunk64(sb + abase, sb + SOF_B + (c % 3) * 16384, warp_m, warp_n, lane, acc);
    }

    // fused pooling epilogue: relu -> horizontal pair max via shuffle -> atomicMax
#pragma unroll
    for (int tf = 0; tf < 2; tf++){
#pragma unroll
        for (int half = 0; half < 2; half++){
            int r = M0 + warp_m * 32 + tf * 16 + (lane >> 2) + half * 8;
#pragma unroll
            for (int j = 0; j < 4; j++){
                float v0 = fmaxf(acc[tf][j][half*2 + 0], 0.f);
                float v1 = fmaxf(acc[tf][j][half*2 + 1], 0.f);
                float m0 = fmaxf(v0, __shfl_xor_sync(0xffffffffu, v0, 4));
                float m1 = fmaxf(v1, __shfl_xor_sync(0xffffffffu, v1, 4));
                if ((((lane >> 2) & 1) == 0) && r < NN){
                    int gr = r / WW, gc = r - gr * WW;
                    int p = (gr >> 1) * PCC + (gc >> 1);
                    int col = warp_n * 32 + j * 8 + (lane & 3) * 2;
                    atomicMax((int*)(out + (size_t)p * 128 + col),     __float_as_int(m0));
                    atomicMax((int*)(out + (size_t)p * 128 + col + 1), __float_as_int(m1));
                }
            }
        }
    }
}

// =====================================================================
// Edge GEMM via fp16 HMMA (XQ gather now fp16 -> raw uint4 copy)
// =====================================================================
__global__ __launch_bounds__(256, 2) void k_edge(const float* __restrict__ efN,
                                                 const float* __restrict__ efE,
                                                 const float* __restrict__ efS,
                                                 const float* __restrict__ efW,
                                                 int unused){
    extern __shared__ char smem[];
    const uint32_t sb = smem_u32(smem);
    const int q = blockIdx.y;
    const float* ef = (q==0) ? efN : (q==1) ? efE : (q==2) ? efS : efW;
    const int E = (q==0 || q==2) ? E_NS : E_EW;
    const int M0 = blockIdx.x * 128;
    if (M0 >= E) return;
    const int tid = threadIdx.x, wid = tid >> 5, lane = tid & 31;

    // fill A: 128 edges x 96 K (12 k8-chunks)
#pragma unroll
    for (int i = 0; i < 6; i++){
        int lin = tid + 256 * i;
        int m = lin / 12, k8c = lin - m * 12;
        int k8 = k8c * 8;
        int e = M0 + m;
        uint4 H = make_uint4(0u, 0u, 0u, 0u);
        if (e < E){
            if (k8c < 4){
                const float* src = ef + (size_t)e * 32 + k8;
                float4 v0 = *(const float4*)(src);
                float4 v1 = *(const float4*)(src + 4);
                H.x = pk_h2(v0.x, v0.y); H.y = pk_h2(v0.z, v0.w);
                H.z = pk_h2(v1.x, v1.y); H.w = pk_h2(v1.z, v1.w);
            } else {
                int s, t;
                if (q == 0){ int r = 1 + e/WW,     c = e%WW;         s = r*WW + c; t = s - WW; }
                else if (q == 1){ int r = e/(WW-1), c = e%(WW-1);    s = r*WW + c; t = s + 1;  }
                else if (q == 2){ int r = e/WW,     c = e%WW;        s = r*WW + c; t = s + WW; }
                else            { int r = e/(WW-1), c = e%(WW-1)+1;  s = r*WW + c; t = s - 1;  }
                int node = (k8c < 8) ? s : t;
                int u = (k8c & 3) * 8;
                H = *(const uint4*)(g_XQ + (size_t)node * 128 + q * 32 + u);
            }
        }
        *(uint4*)(smem + EOF_A + swoff256(m, k8)) = H;
    }
    {
        const uint4* bh = (const uint4*)g_BE[q];
#pragma unroll
        for (int i = 0; i < 2; i++){
            int idx = tid + 256 * i;
            ((uint4*)(smem + EOF_B))[idx] = bh[idx];
        }
    }
    __syncthreads();

    float acc[4][4];
#pragma unroll
    for (int j = 0; j < 4; j++)
#pragma unroll
        for (int e = 0; e < 4; e++) acc[j][e] = 0.f;

#pragma unroll
    for (int kc = 0; kc < 6; kc++){
        uint32_t a[4];
        {
            int row = wid * 16 + (lane & 15);
            int ch = kc * 2 + (lane >> 4);
            uint32_t off = row * 256 + ((ch ^ (row & 7)) << 4);
            LDSM_X4(a[0], a[1], a[2], a[3], sb + EOF_A + off);
        }
        uint32_t bfr[4][2];
#pragma unroll
        for (int jj = 0; jj < 2; jj++){
            int rowN = jj * 16 + (lane & 7) + ((lane >> 4) << 3);
            int ch = kc * 2 + ((lane >> 3) & 1);
            uint32_t off = rowN * 256 + ((ch ^ (rowN & 7)) << 4);
            uint32_t r0, r1, r2, r3;
            LDSM_X4(r0, r1, r2, r3, sb + EOF_B + off);
            bfr[jj*2][0] = r0;   bfr[jj*2][1] = r1;
            bfr[jj*2+1][0] = r2; bfr[jj*2+1][1] = r3;
        }
#pragma unroll
        for (int j = 0; j < 4; j++)
            mma_f16(acc[j], a, bfr[j][0], bfr[j][1]);
    }

    float* ED = &g_EDGE[q][0];
    int r0 = M0 + wid * 16 + (lane >> 2);
#pragma unroll
    for (int j = 0; j < 4; j++){
        int col = j * 8 + (lane & 3) * 2;
        if (r0 < E)
            *(float2*)(ED + (size_t)r0 * 32 + col) =
                make_float2(fmaxf(acc[j][0], 0.f), fmaxf(acc[j][1], 0.f));
        if (r0 + 8 < E)
            *(float2*)(ED + (size_t)(r0 + 8) * 32 + col) =
                make_float2(fmaxf(acc[j][2], 0.f), fmaxf(acc[j][3], 0.f));
    }
}

// ---------------- metadata / edge-feature kernels ----------------
__global__ void k_meta(float* __restrict__ out){
    int t = blockIdx.x * 256 + threadIdx.x;
    if (t < NP){
        out[OFF_POS + 2*t]     = (float)(t / PCC);
        out[OFF_POS + 2*t + 1] = (float)(t % PCC);
        return;
    }
    t -= NP;
    if (t < M_NS){
        int k = 1 + t / PCC, j = t % PCC;
        out[OFF_EIN + 2*t]     = (float)(k*PCC + j);
        out[OFF_EIN + 2*t + 1] = (float)((k-1)*PCC + j);
        return;
    }
    t -= M_NS;
    if (t < M_EW){
        int k = t / 217, j = t % 217;
        int s = k*PCC + j;
        out[OFF_EIE + 2*t]     = (float)s;
        out[OFF_EIE + 2*t + 1] = (float)(s + 1);
        return;
    }
    t -= M_EW;
    if (t < M_NS){
        int k = t / PCC, j = t % PCC;
        int s = k*PCC + j;
        out[OFF_EIS + 2*t]     = (float)s;
        out[OFF_EIS + 2*t + 1] = (float)(s + PCC);
        return;
    }
    t -= M_NS;
    if (t < M_EW){
        int k = t / 217, j = t % 217 + 1;
        int s = k*PCC + j;
        out[OFF_EIW + 2*t]     = (float)s;
        out[OFF_EIW + 2*t + 1] = (float)(s - 1);
        return;
    }
}

__global__ void k_efeat(float* __restrict__ out){
    const int d = blockIdx.y;
    const int M = (d == 0 || d == 2) ? M_NS : M_EW;
    int t = blockIdx.x * 256 + threadIdx.x;
    if (t >= M * 8) return;
    int m = t >> 3, fi = (t & 7) * 4;
    int e1, stride2 = 1; bool two = true; size_t off;
    if (d == 0){      int k = 1 + m/PCC, j = m%PCC; e1 = (2*k - 1)*WW + 2*j;      off = OFF_FN; }
    else if (d == 1){ int k = m/217,     j = m%217; e1 = 2*k*(WW-1) + 2*j + 1;    stride2 = WW-1; two = (k < 247); off = OFF_FE; }
    else if (d == 2){ int k = m/PCC,     j = m%PCC; e1 = (2*k + 1)*WW + 2*j;      off = OFF_FS; }
    else {            int k = m/217,     j = m%217 + 1; e1 = 2*k*(WW-1) + 2*j - 1; stride2 = WW-1; two = (k < 247); off = OFF_FW; }
    const float* ED = &g_EDGE[d][0];
    float4 a = *(const float4*)(ED + (size_t)e1*32 + fi);
    if (two){
        float4 b = *(const float4*)(ED + (size_t)(e1 + stride2)*32 + fi);
        a.x = fmaxf(a.x, b.x); a.y = fmaxf(a.y, b.y);
        a.z = fmaxf(a.z, b.z); a.w = fmaxf(a.w, b.w);
    }
    float* o = out + off + (size_t)m*32 + fi;
    o[0] = a.x; o[1] = a.y; o[2] = a.z; o[3] = a.w;
}

// =====================================================================
extern "C" void kernel_launch(void* const* d_in, const int* in_sizes, int n_in,
                              void* d_out, int out_size){
    const float* x     = (const float*)d_in[0];
    const float* efN   = (const float*)d_in[6];
    const float* efE   = (const float*)d_in[7];
    const float* efS   = (const float*)d_in[8];
    const float* efW   = (const float*)d_in[9];
    const float* Wemb  = (const float*)d_in[10];
    const float* Wedge = (const float*)d_in[11];
    const float* Wnode = (const float*)d_in[12];
    float* out = (float*)d_out;

    static bool attr_done = false;
    if (!attr_done){
        cudaFuncSetAttribute(k_tg1, cudaFuncAttributeMaxDynamicSharedMemorySize, SMEM_TG);
        cudaFuncSetAttribute(k_tg2, cudaFuncAttributeMaxDynamicSharedMemorySize, SMEM_TG);
        cudaFuncSetAttribute(k_edge, cudaFuncAttributeMaxDynamicSharedMemorySize, SMEM_TE);
        attr_done = true;
    }

    const int gm = (NN + 127) / 128;             // 1687 tiles
    k_conv_w<<<(65536 + 255)/256, 256>>>(Wemb, Wnode, Wedge);
    k_init<<<(NP*32 + 255)/256, 256>>>(out);
    k_tg1<<<gm, 512, SMEM_TG>>>(x);
    dim3 ge((E_NS + 127) / 128, 4);
    k_edge<<<ge, 256, SMEM_TE>>>(efN, efE, efS, efW, 0);
    k_tg2<<<gm, 512, SMEM_TG>>>(x, out);

    const int metaT = NP + 2*M_NS + 2*M_EW;
    dim3 gf((M_NS*8 + 255) / 256, 4);
    k_meta<<<(metaT + 255)/256, 256>>>(out);
    k_efeat<<<gf, 256>>>(out);
}